// round 3
// baseline (speedup 1.0000x reference)
#include <cuda_runtime.h>
#include <math.h>

#define BB   32
#define NSEQ 512
#define DIN  256
#define DH   128
#define NITER 10
#define NM   (NSEQ*NSEQ)
#define HS   (BB*NSEQ*DH)

// ---------------- device scratch (no runtime allocation) ----------------
static __device__ float  g_H0[HS];
static __device__ float  g_M0[HS];
static __device__ float  g_Hb[2*HS];
static __device__ float  g_Mb[2*HS];
static __device__ float  g_T[HS];
static __device__ float  g_scores[BB*NM];
static __device__ float  g_W[BB*NM];      // Lhat -> in-place GJ result (cols scrambled)
static __device__ float  g_BT[BB*NM];     // BT[j][i] = Binv[i][j]
static __device__ float  g_Y[BB*NM];
static __device__ float  g_c[BB];
static __device__ float  g_S[BB*NSEQ];    // column sums of At
static __device__ double g_logdet[BB];
static __device__ double g_dotp[BB];
static __device__ float  g_diagB[BB*NSEQ];  // Binv[j][j]
static __device__ float  g_rootB[BB*NSEQ];  // Binv[j][0]
static __device__ int    g_perm[BB*NSEQ];

// ---------------- generic tiled GEMM: C[bz] = opA @ opB (+ epilogue) ----------------
// 64x64 tile, BK=16, 256 threads, 4x4 micro-tile. All dims multiples of 64/16.
// EPI: 0 plain, 1 add bias vector C0[N], 2 relu(C0 + acc) with C0 shaped like C.
template<bool TA, bool TB, int EPI>
__global__ void __launch_bounds__(256) gemm_k(
    const float* __restrict__ A, const float* __restrict__ B,
    const float* __restrict__ C0, float* __restrict__ C,
    int M, int N, int K, int lda, int ldb, int ldc,
    long sA, long sB, long sC)
{
    int bz = blockIdx.z;
    A += (long)bz * sA;  B += (long)bz * sB;  C += (long)bz * sC;

    __shared__ float As[16][64];
    __shared__ float Bs[16][64];

    int tid = threadIdx.x;
    int i0 = blockIdx.y * 64, j0 = blockIdx.x * 64;
    int tx = tid & 15, ty = tid >> 4;

    float acc[4][4] = {};

    for (int k0 = 0; k0 < K; k0 += 16) {
        if (!TA) {
            int i = tid >> 2, kk = (tid & 3) << 2;
            float4 v = *(const float4*)(A + (long)(i0 + i) * lda + k0 + kk);
            As[kk + 0][i] = v.x; As[kk + 1][i] = v.y; As[kk + 2][i] = v.z; As[kk + 3][i] = v.w;
        } else {
            int kk = tid >> 4, i4 = (tid & 15) << 2;
            float4 v = *(const float4*)(A + (long)(k0 + kk) * lda + i0 + i4);
            *(float4*)&As[kk][i4] = v;
        }
        if (!TB) {
            int kk = tid >> 4, j4 = (tid & 15) << 2;
            float4 v = *(const float4*)(B + (long)(k0 + kk) * ldb + j0 + j4);
            *(float4*)&Bs[kk][j4] = v;
        } else {
            int j = tid >> 2, kk = (tid & 3) << 2;
            float4 v = *(const float4*)(B + (long)(j0 + j) * ldb + k0 + kk);
            Bs[kk + 0][j] = v.x; Bs[kk + 1][j] = v.y; Bs[kk + 2][j] = v.z; Bs[kk + 3][j] = v.w;
        }
        __syncthreads();
        #pragma unroll
        for (int kk = 0; kk < 16; kk++) {
            float4 av = *(const float4*)&As[kk][ty << 2];
            float4 bv = *(const float4*)&Bs[kk][tx << 2];
            float ar[4] = {av.x, av.y, av.z, av.w};
            float br[4] = {bv.x, bv.y, bv.z, bv.w};
            #pragma unroll
            for (int a = 0; a < 4; a++)
                #pragma unroll
                for (int q = 0; q < 4; q++)
                    acc[a][q] = fmaf(ar[a], br[q], acc[a][q]);
        }
        __syncthreads();
    }

    #pragma unroll
    for (int a = 0; a < 4; a++) {
        int row = i0 + (ty << 2) + a;
        long off = (long)row * ldc + j0 + (tx << 2);
        float4 r = make_float4(acc[a][0], acc[a][1], acc[a][2], acc[a][3]);
        if (EPI == 1) {
            float4 bb = *(const float4*)(C0 + j0 + (tx << 2));
            r.x += bb.x; r.y += bb.y; r.z += bb.z; r.w += bb.w;
        }
        if (EPI == 2) {
            float4 cv = *(const float4*)(C0 + off);
            r.x = fmaxf(cv.x + r.x, 0.f); r.y = fmaxf(cv.y + r.y, 0.f);
            r.z = fmaxf(cv.z + r.z, 0.f); r.w = fmaxf(cv.w + r.w, 0.f);
        }
        *(float4*)(C + off) = r;
    }
}

__global__ void relu_k(const float* __restrict__ s, float* __restrict__ d, int n) {
    int i = blockIdx.x * blockDim.x + threadIdx.x;
    if (i < n) d[i] = fmaxf(s[i], 0.f);
}

// ---------------- c[b] = max over pair-masked scores; also zero dot accumulator ----------------
__global__ void __launch_bounds__(1024) cmax_k(const int* __restrict__ lengths) {
    int b = blockIdx.x, len = lengths[b];
    const float* s = g_scores + (size_t)b * NM;
    float best = -1e30f;
    for (int idx = threadIdx.x; idx < NM; idx += 1024) {
        int h = idx >> 9, m = idx & 511;
        if (h <= len && m >= 1 && m <= len && h != m) {
            float v = s[idx];
            if (v > best) best = v;
        }
    }
    __shared__ float sr[1024];
    sr[threadIdx.x] = best; __syncthreads();
    for (int o = 512; o; o >>= 1) {
        if (threadIdx.x < o) { float v = sr[threadIdx.x + o]; if (v > sr[threadIdx.x]) sr[threadIdx.x] = v; }
        __syncthreads();
    }
    if (threadIdx.x == 0) { g_c[b] = sr[0]; g_dotp[b] = 0.0; }
}

// ---------------- colsum[j] = sum_{h=1..len, h!=m} exp(s[h,m]-c), m=j+1 ----------------
__global__ void colsum_k(const int* __restrict__ lengths) {
    int b = blockIdx.x, j = threadIdx.x, m = j + 1, len = lengths[b];
    float c = g_c[b], s = 0.f;
    if (m < NSEQ && m <= len) {
        const float* sc = g_scores + (size_t)b * NM;
        for (int h = 1; h <= len; h++)
            if (h != m) s += expf(sc[h * NSEQ + m] - c);
    }
    g_S[b * NSEQ + j] = s;
}

// ---------------- build padded 512x512 Lhat ----------------
__global__ void lhat_k(const int* __restrict__ lengths) {
    int i = blockIdx.x, b = blockIdx.y, j = threadIdx.x, len = lengths[b];
    float c = g_c[b];
    const float* sc = g_scores + (size_t)b * NM;
    float v;
    if (i == NSEQ - 1)      v = (j == NSEQ - 1) ? 1.f : 0.f;
    else if (j == NSEQ - 1) v = 0.f;
    else if (i == 0) { int m = j + 1; v = (m <= len) ? expf(sc[m] - c) : 0.f; }
    else if (j == i) {
        int m = i + 1;
        float r = (m <= len) ? expf(sc[m] - c) : 0.f;
        v = r + g_S[b * NSEQ + i] + ((m <= len) ? 0.f : 1.f);
    } else {
        int h = i + 1, m = j + 1;
        v = (h <= len && m <= len) ? -expf(sc[h * NSEQ + m] - c) : 0.f;
    }
    g_W[(size_t)b * NM + (size_t)i * NSEQ + j] = v;
}

// ---------------- in-place Gauss-Jordan inverse with partial pivoting ----------------
// One CTA (1024 thr) per batch matrix. Emits scrambled inverse in g_W, column labels
// g_perm (Binv[i][j] = C[i][L[j]]), and logdet (fp64 accumulation).
__global__ void __launch_bounds__(1024) gj_k() {
    int b = blockIdx.x, tid = threadIdx.x;
    float* W = g_W + (size_t)b * NM;
    __shared__ __align__(16) float s_row[NSEQ];
    __shared__ float s_col[NSEQ];
    __shared__ float red_v[32]; __shared__ int red_i[32];
    __shared__ int s_piv[NSEQ];
    __shared__ int s_L[NSEQ];
    __shared__ float sh_pivinv; __shared__ int sh_p; __shared__ double sh_ld;
    if (tid == 0) sh_ld = 0.0;
    __syncthreads();

    for (int k = 0; k < NSEQ; k++) {
        // pivot search: argmax |W[i][k]|, i in [k,511]
        float best = -1.f; int bi = k;
        for (int i = k + tid; i < NSEQ; i += 1024) {
            float v = fabsf(W[(size_t)i * NSEQ + k]);
            if (v > best) { best = v; bi = i; }
        }
        #pragma unroll
        for (int o = 16; o; o >>= 1) {
            float ov = __shfl_down_sync(0xffffffffu, best, o);
            int   oi = __shfl_down_sync(0xffffffffu, bi, o);
            if (ov > best) { best = ov; bi = oi; }
        }
        if ((tid & 31) == 0) { red_v[tid >> 5] = best; red_i[tid >> 5] = bi; }
        __syncthreads();
        if (tid < 32) {
            best = red_v[tid]; bi = red_i[tid];
            #pragma unroll
            for (int o = 16; o; o >>= 1) {
                float ov = __shfl_down_sync(0xffffffffu, best, o);
                int   oi = __shfl_down_sync(0xffffffffu, bi, o);
                if (ov > best) { best = ov; bi = oi; }
            }
            if (tid == 0) { sh_p = bi; s_piv[k] = bi; }
        }
        __syncthreads();
        int p = sh_p;
        if (p != k) {
            if (tid < 128) {
                float4* rk = (float4*)(W + (size_t)k * NSEQ);
                float4* rp = (float4*)(W + (size_t)p * NSEQ);
                float4 a = rk[tid], c4 = rp[tid]; rk[tid] = c4; rp[tid] = a;
            }
            __syncthreads();
        }
        if (tid == 0) {
            float piv = W[(size_t)k * NSEQ + k];
            sh_pivinv = 1.f / piv;
            sh_ld += log(fabs((double)piv));
        }
        __syncthreads();
        float pivinv = sh_pivinv;
        if (tid < NSEQ) {
            s_col[tid] = W[(size_t)tid * NSEQ + k];
            // s_row[k] = 1+pivinv makes the generic update produce W[i][k] = -c_i*pivinv
            s_row[tid] = (tid == k) ? (1.f + pivinv) : (W[(size_t)k * NSEQ + tid] * pivinv);
        }
        __syncthreads();
        int kc = k >> 2, kl = k & 3;
        for (int t = tid; t < NSEQ * 128; t += 1024) {
            int i = t >> 7, ch = t & 127;
            float4* wp = (float4*)W + (size_t)i * 128 + ch;
            float4 r4 = *(const float4*)(s_row + (ch << 2));
            if (i == k) {
                float4 v = r4;
                if (ch == kc) ((float*)&v)[kl] = pivinv;
                *wp = v;
            } else {
                float cm = s_col[i];
                float4 w = *wp;
                w.x = fmaf(-cm, r4.x, w.x); w.y = fmaf(-cm, r4.y, w.y);
                w.z = fmaf(-cm, r4.z, w.z); w.w = fmaf(-cm, r4.w, w.w);
                *wp = w;
            }
        }
        __syncthreads();
    }
    if (tid == 0) {
        g_logdet[b] = sh_ld;
        for (int j = 0; j < NSEQ; j++) s_L[j] = j;
        for (int k = NSEQ - 1; k >= 0; k--) {
            int p = s_piv[k];
            if (p != k) { int t = s_L[k]; s_L[k] = s_L[p]; s_L[p] = t; }
        }
    }
    __syncthreads();
    for (int j = tid; j < NSEQ; j += 1024) g_perm[b * NSEQ + j] = s_L[j];
}

// ---------------- BT[j][i] = Binv[i][j] = C[i][L[j]]; also diag and column 0 ----------------
__global__ void perm_k() {
    int j = blockIdx.x, b = blockIdx.y, i = threadIdx.x;
    const float* C = g_W + (size_t)b * NM;
    int Lj = g_perm[b * NSEQ + j];
    float v = C[(size_t)i * NSEQ + Lj];
    g_BT[(size_t)b * NM + (size_t)j * NSEQ + i] = v;
    if (i == j) g_diagB[b * NSEQ + j] = v;
    if (j == 0) g_rootB[b * NSEQ + i] = v;   // Binv[i][0]
}

// ---------------- marginals Y + fp64 dot(Y, scores) ----------------
__global__ void __launch_bounds__(512) y_k(const int* __restrict__ lengths) {
    int h = blockIdx.x, b = blockIdx.y, m = threadIdx.x;
    int len = lengths[b];
    float c = g_c[b];
    float s = g_scores[(size_t)b * NM + (size_t)h * NSEQ + m];
    float y = 0.f;
    if (h <= len && m >= 1 && m <= len && h != m) {
        float A = expf(s - c);
        float diag = (m >= 2) ? g_diagB[b * NSEQ + (m - 1)] : 0.f;
        float G;
        if (h == 0) G = g_rootB[b * NSEQ + (m - 1)] + diag;
        else        G = diag - ((h >= 2) ? g_BT[(size_t)b * NM + (size_t)(h - 1) * NSEQ + (m - 1)] : 0.f);
        y = A * G;
    }
    g_Y[(size_t)b * NM + (size_t)h * NSEQ + m] = y;

    float v = y * s;
    #pragma unroll
    for (int o = 16; o; o >>= 1) v += __shfl_down_sync(0xffffffffu, v, o);
    __shared__ float ws[16];
    if ((m & 31) == 0) ws[m >> 5] = v;
    __syncthreads();
    if (m < 16) {
        v = ws[m];
        #pragma unroll
        for (int o = 8; o; o >>= 1) v += __shfl_down_sync(0xffffu, v, o);
        if (m == 0) atomicAdd(&g_dotp[b], (double)v);
    }
}

// ---------------- finalize logZ and entr into the output ----------------
__global__ void fin_k(const int* __restrict__ lengths, float* __restrict__ out) {
    int b = threadIdx.x;
    if (b < BB) {
        float logZ = (float)g_logdet[b] + (float)lengths[b] * g_c[b];
        out[(size_t)BB * NM + b] = logZ;                              // logZ block
        out[(size_t)2 * BB * NM + BB + b] = logZ - (float)g_dotp[b];  // entr block
    }
}

extern "C" void kernel_launch(void* const* d_in, const int* in_sizes, int n_in,
                              void* d_out, int out_size) {
    const float* Xh = (const float*)d_in[0];
    const float* Xm = (const float*)d_in[1];
    const int*   lengths = (const int*)d_in[2];
    const float* Wh = (const float*)d_in[3];
    const float* bh = (const float*)d_in[4];
    const float* Wm = (const float*)d_in[5];
    const float* bm = (const float*)d_in[6];
    const float* V  = (const float*)d_in[7];
    float* out = (float*)d_out;

    void* p;
    cudaGetSymbolAddress(&p, g_H0);     float* pH0 = (float*)p;
    cudaGetSymbolAddress(&p, g_M0);     float* pM0 = (float*)p;
    cudaGetSymbolAddress(&p, g_Hb);     float* pHb = (float*)p;
    cudaGetSymbolAddress(&p, g_Mb);     float* pMb = (float*)p;
    cudaGetSymbolAddress(&p, g_T);      float* pT  = (float*)p;
    cudaGetSymbolAddress(&p, g_scores); float* pSc = (float*)p;
    cudaGetSymbolAddress(&p, g_Y);      float* pY  = (float*)p;

    dim3 gProj(DH / 64, (BB * NSEQ) / 64, 1);  // (2, 256)

    // projections + relu
    gemm_k<false, true, 1><<<gProj, 256>>>(Xh, Wh, bh, pH0, BB*NSEQ, DH, DIN, DIN, DIN, DH, 0, 0, 0);
    gemm_k<false, true, 1><<<gProj, 256>>>(Xm, Wm, bm, pM0, BB*NSEQ, DH, DIN, DIN, DIN, DH, 0, 0, 0);
    relu_k<<<(HS + 255) / 256, 256>>>(pH0, pHb, HS);
    relu_k<<<(HS + 255) / 256, 256>>>(pM0, pMb, HS);

    for (int it = 0; it < NITER; it++) {
        float* H = pHb + (size_t)(it & 1) * HS;
        float* M = pMb + (size_t)(it & 1) * HS;
        // T = H @ V  (flattened over batch)
        gemm_k<false, false, 0><<<gProj, 256>>>(H, V, nullptr, pT, BB*NSEQ, DH, DH, DH, DH, DH, 0, 0, 0);
        // scores = T @ M^T  (batched)
        gemm_k<false, true, 0><<<dim3(8, 8, BB), 256>>>(pT, M, nullptr, pSc, NSEQ, NSEQ, DH,
                                                        DH, DH, NSEQ, (long)NSEQ*DH, (long)NSEQ*DH, (long)NM);
        cmax_k<<<BB, 1024>>>(lengths);
        colsum_k<<<BB, NSEQ>>>(lengths);
        lhat_k<<<dim3(NSEQ, BB), NSEQ>>>(lengths);
        gj_k<<<BB, 1024>>>();
        perm_k<<<dim3(NSEQ, BB), NSEQ>>>();
        y_k<<<dim3(NSEQ, BB), NSEQ>>>(lengths);

        if (it < NITER - 1) {
            float* Hn = pHb + (size_t)((it + 1) & 1) * HS;
            float* Mn = pMb + (size_t)((it + 1) & 1) * HS;
            // T = Y @ M  (batched)
            gemm_k<false, false, 0><<<dim3(2, 8, BB), 256>>>(pY, M, nullptr, pT, NSEQ, DH, NSEQ,
                                                             NSEQ, DH, DH, (long)NM, (long)NSEQ*DH, (long)NSEQ*DH);
            // Hn = relu(H0 + T @ V^T)
            gemm_k<false, true, 2><<<gProj, 256>>>(pT, V, pH0, Hn, BB*NSEQ, DH, DH, DH, DH, DH, 0, 0, 0);
            // T = Y^T @ H  (batched)
            gemm_k<true, false, 0><<<dim3(2, 8, BB), 256>>>(pY, H, nullptr, pT, NSEQ, DH, NSEQ,
                                                            NSEQ, DH, DH, (long)NM, (long)NSEQ*DH, (long)NSEQ*DH);
            // Mn = relu(M0 + T @ V)
            gemm_k<false, false, 2><<<gProj, 256>>>(pT, V, pM0, Mn, BB*NSEQ, DH, DH, DH, DH, DH, 0, 0, 0);
        }
    }

    fin_k<<<1, BB>>>(lengths, out);
    cudaMemcpyAsync(out, pSc, (size_t)BB * NM * sizeof(float), cudaMemcpyDeviceToDevice, 0);
    cudaMemcpyAsync(out + (size_t)BB * NM + BB, pY, (size_t)BB * NM * sizeof(float), cudaMemcpyDeviceToDevice, 0);
}

// round 4
// speedup vs baseline: 2.6327x; 2.6327x over previous
#include <cuda_runtime.h>
#include <math.h>

#define BB   32
#define NSEQ 512
#define DIN  256
#define DH   128
#define NITER 10
#define NM   (NSEQ*NSEQ)
#define HS   (BB*NSEQ*DH)
#define NB   16
#define GJ_SMEM ((NSEQ*17 + NB*NSEQ) * 4)

// ---------------- device scratch (no runtime allocation) ----------------
static __device__ float  g_H0[HS];
static __device__ float  g_M0[HS];
static __device__ float  g_Hb[2*HS];
static __device__ float  g_Mb[2*HS];
static __device__ float  g_T[HS];
static __device__ float  g_scores[BB*NM];
static __device__ float  g_W[BB*NM];      // Lhat -> in-place GJ result (cols scrambled)
static __device__ float  g_BT[BB*NM];     // BT[j][i] = Binv[i][j]
static __device__ float  g_Y[BB*NM];
static __device__ float  g_c[BB];
static __device__ float  g_S[BB*NSEQ];    // column sums of At
static __device__ double g_logdet[BB];
static __device__ double g_dotp[BB];
static __device__ float  g_diagB[BB*NSEQ];  // Binv[j][j]
static __device__ float  g_rootB[BB*NSEQ];  // Binv[j][0]
static __device__ int    g_perm[BB*NSEQ];

// ---------------- generic tiled GEMM: C[bz] = opA @ opB (+ epilogue) ----------------
// 64x64 tile, BK=16, 256 threads, 4x4 micro-tile. All dims multiples of 64/16.
// EPI: 0 plain, 1 add bias vector C0[N], 2 relu(C0 + acc) with C0 shaped like C.
template<bool TA, bool TB, int EPI>
__global__ void __launch_bounds__(256) gemm_k(
    const float* __restrict__ A, const float* __restrict__ B,
    const float* __restrict__ C0, float* __restrict__ C,
    int M, int N, int K, int lda, int ldb, int ldc,
    long sA, long sB, long sC)
{
    int bz = blockIdx.z;
    A += (long)bz * sA;  B += (long)bz * sB;  C += (long)bz * sC;

    __shared__ float As[16][64];
    __shared__ float Bs[16][64];

    int tid = threadIdx.x;
    int i0 = blockIdx.y * 64, j0 = blockIdx.x * 64;
    int tx = tid & 15, ty = tid >> 4;

    float acc[4][4] = {};

    for (int k0 = 0; k0 < K; k0 += 16) {
        if (!TA) {
            int i = tid >> 2, kk = (tid & 3) << 2;
            float4 v = *(const float4*)(A + (long)(i0 + i) * lda + k0 + kk);
            As[kk + 0][i] = v.x; As[kk + 1][i] = v.y; As[kk + 2][i] = v.z; As[kk + 3][i] = v.w;
        } else {
            int kk = tid >> 4, i4 = (tid & 15) << 2;
            float4 v = *(const float4*)(A + (long)(k0 + kk) * lda + i0 + i4);
            *(float4*)&As[kk][i4] = v;
        }
        if (!TB) {
            int kk = tid >> 4, j4 = (tid & 15) << 2;
            float4 v = *(const float4*)(B + (long)(k0 + kk) * ldb + j0 + j4);
            *(float4*)&Bs[kk][j4] = v;
        } else {
            int j = tid >> 2, kk = (tid & 3) << 2;
            float4 v = *(const float4*)(B + (long)(j0 + j) * ldb + k0 + kk);
            Bs[kk + 0][j] = v.x; Bs[kk + 1][j] = v.y; Bs[kk + 2][j] = v.z; Bs[kk + 3][j] = v.w;
        }
        __syncthreads();
        #pragma unroll
        for (int kk = 0; kk < 16; kk++) {
            float4 av = *(const float4*)&As[kk][ty << 2];
            float4 bv = *(const float4*)&Bs[kk][tx << 2];
            float ar[4] = {av.x, av.y, av.z, av.w};
            float br[4] = {bv.x, bv.y, bv.z, bv.w};
            #pragma unroll
            for (int a = 0; a < 4; a++)
                #pragma unroll
                for (int q = 0; q < 4; q++)
                    acc[a][q] = fmaf(ar[a], br[q], acc[a][q]);
        }
        __syncthreads();
    }

    #pragma unroll
    for (int a = 0; a < 4; a++) {
        int row = i0 + (ty << 2) + a;
        long off = (long)row * ldc + j0 + (tx << 2);
        float4 r = make_float4(acc[a][0], acc[a][1], acc[a][2], acc[a][3]);
        if (EPI == 1) {
            float4 bb = *(const float4*)(C0 + j0 + (tx << 2));
            r.x += bb.x; r.y += bb.y; r.z += bb.z; r.w += bb.w;
        }
        if (EPI == 2) {
            float4 cv = *(const float4*)(C0 + off);
            r.x = fmaxf(cv.x + r.x, 0.f); r.y = fmaxf(cv.y + r.y, 0.f);
            r.z = fmaxf(cv.z + r.z, 0.f); r.w = fmaxf(cv.w + r.w, 0.f);
        }
        *(float4*)(C + off) = r;
    }
}

__global__ void relu_k(const float* __restrict__ s, float* __restrict__ d, int n) {
    int i = blockIdx.x * blockDim.x + threadIdx.x;
    if (i < n) d[i] = fmaxf(s[i], 0.f);
}

// ---------------- c[b] = max over pair-masked scores; also zero dot accumulator ----------------
__global__ void __launch_bounds__(1024) cmax_k(const int* __restrict__ lengths) {
    int b = blockIdx.x, len = lengths[b];
    const float* s = g_scores + (size_t)b * NM;
    float best = -1e30f;
    for (int idx = threadIdx.x; idx < NM; idx += 1024) {
        int h = idx >> 9, m = idx & 511;
        if (h <= len && m >= 1 && m <= len && h != m) {
            float v = s[idx];
            if (v > best) best = v;
        }
    }
    __shared__ float sr[1024];
    sr[threadIdx.x] = best; __syncthreads();
    for (int o = 512; o; o >>= 1) {
        if (threadIdx.x < o) { float v = sr[threadIdx.x + o]; if (v > sr[threadIdx.x]) sr[threadIdx.x] = v; }
        __syncthreads();
    }
    if (threadIdx.x == 0) { g_c[b] = sr[0]; g_dotp[b] = 0.0; }
}

// ---------------- colsum[j] = sum_{h=1..len, h!=m} exp(s[h,m]-c), m=j+1 ----------------
__global__ void colsum_k(const int* __restrict__ lengths) {
    int b = blockIdx.x, j = threadIdx.x, m = j + 1, len = lengths[b];
    float c = g_c[b], s = 0.f;
    if (m < NSEQ && m <= len) {
        const float* sc = g_scores + (size_t)b * NM;
        for (int h = 1; h <= len; h++)
            if (h != m) s += expf(sc[h * NSEQ + m] - c);
    }
    g_S[b * NSEQ + j] = s;
}

// ---------------- build padded 512x512 Lhat ----------------
__global__ void lhat_k(const int* __restrict__ lengths) {
    int i = blockIdx.x, b = blockIdx.y, j = threadIdx.x, len = lengths[b];
    float c = g_c[b];
    const float* sc = g_scores + (size_t)b * NM;
    float v;
    if (i == NSEQ - 1)      v = (j == NSEQ - 1) ? 1.f : 0.f;
    else if (j == NSEQ - 1) v = 0.f;
    else if (i == 0) { int m = j + 1; v = (m <= len) ? expf(sc[m] - c) : 0.f; }
    else if (j == i) {
        int m = i + 1;
        float r = (m <= len) ? expf(sc[m] - c) : 0.f;
        v = r + g_S[b * NSEQ + i] + ((m <= len) ? 0.f : 1.f);
    } else {
        int h = i + 1, m = j + 1;
        v = (h <= len && m <= len) ? -expf(sc[h * NSEQ + m] - c) : 0.f;
    }
    g_W[(size_t)b * NM + (size_t)i * NSEQ + j] = v;
}

// ---------------- blocked in-place Gauss-Jordan inverse with partial pivoting ----------------
// One CTA (1024 thr) per matrix. NB=16 panel factored in smem, rank-16 trailing update.
// Emits scrambled inverse in g_W (Binv[i][j] = C[i][L[j]]), labels g_perm, fp64 logdet.
__global__ void __launch_bounds__(1024, 1) gjb_k() {
    int b = blockIdx.x, tid = threadIdx.x;
    float* W = g_W + (size_t)b * NM;
    extern __shared__ float sm[];
    float* Ap = sm;                 // panel [512][17] (padded)
    float* Wp = sm + NSEQ * 17;     // swapped panel rows [16][512]
    __shared__ float red_v[32]; __shared__ int red_i[32];
    __shared__ int s_piv[NSEQ];
    __shared__ int s_L[NSEQ];
    __shared__ float s_col[NSEQ];
    __shared__ float s_row16[NB];
    __shared__ float sh_pivinv; __shared__ int sh_p; __shared__ double sh_ld;
    if (tid == 0) sh_ld = 0.0;

    for (int k0 = 0; k0 < NSEQ; k0 += NB) {
        __syncthreads();
        // ---- load panel columns k0..k0+15 into smem ----
        for (int t = tid; t < NSEQ * NB; t += 1024) {
            int i = t >> 4, j = t & 15;
            Ap[i * 17 + j] = W[(size_t)i * NSEQ + k0 + j];
        }
        __syncthreads();

        // ---- factor panel (16 GJ steps, all in smem) ----
        for (int j = 0; j < NB; j++) {
            int k = k0 + j;
            float best = -1.f; int bi = k;
            for (int i = k + tid; i < NSEQ; i += 1024) {
                float v = fabsf(Ap[i * 17 + j]);
                if (v > best) { best = v; bi = i; }
            }
            #pragma unroll
            for (int o = 16; o; o >>= 1) {
                float ov = __shfl_down_sync(0xffffffffu, best, o);
                int   oi = __shfl_down_sync(0xffffffffu, bi, o);
                if (ov > best) { best = ov; bi = oi; }
            }
            if ((tid & 31) == 0) { red_v[tid >> 5] = best; red_i[tid >> 5] = bi; }
            __syncthreads();
            if (tid < 32) {
                best = red_v[tid]; bi = red_i[tid];
                #pragma unroll
                for (int o = 16; o; o >>= 1) {
                    float ov = __shfl_down_sync(0xffffffffu, best, o);
                    int   oi = __shfl_down_sync(0xffffffffu, bi, o);
                    if (ov > best) { best = ov; bi = oi; }
                }
                if (tid == 0) { sh_p = bi; s_piv[k] = bi; }
            }
            __syncthreads();
            int p = sh_p;
            if (p != k && tid < NB) {
                float t1 = Ap[k * 17 + tid];
                Ap[k * 17 + tid] = Ap[p * 17 + tid];
                Ap[p * 17 + tid] = t1;
            }
            __syncthreads();
            if (tid == 0) {
                float piv = Ap[k * 17 + j];
                sh_pivinv = 1.f / piv;
                sh_ld += log(fabs((double)piv));
            }
            __syncthreads();
            float pivinv = sh_pivinv;
            if (tid < NB) s_row16[tid] = (tid == j) ? (1.f + pivinv) : Ap[k * 17 + tid] * pivinv;
            if (tid < NSEQ) s_col[tid] = Ap[tid * 17 + j];
            __syncthreads();
            for (int t = tid; t < NSEQ * NB; t += 1024) {
                int i = t >> 4, jj = t & 15;
                float v;
                if (i == k) v = (jj == j) ? pivinv : s_row16[jj];
                else        v = fmaf(-s_col[i], s_row16[jj], Ap[i * 17 + jj]);
                Ap[i * 17 + jj] = v;
            }
            __syncthreads();
        }

        // ---- apply the 16 row swaps to gmem (order matters) ----
        for (int j = 0; j < NB; j++) {
            int k = k0 + j, p = s_piv[k];
            if (p != k) {
                if (tid < 128) {
                    float4* rk = (float4*)(W + (size_t)k * NSEQ);
                    float4* rp = (float4*)(W + (size_t)p * NSEQ);
                    float4 a = rk[tid], c4 = rp[tid];
                    rk[tid] = c4; rp[tid] = a;
                }
                __syncthreads();
            }
        }

        // ---- buffer swapped panel rows into Wp (float4 coalesced) ----
        for (int t = tid; t < NB * 128; t += 1024) {
            int j = t >> 7, c4 = t & 127;
            ((float4*)(Wp + j * NSEQ))[c4] = ((const float4*)(W + (size_t)(k0 + j) * NSEQ))[c4];
        }
        // ---- write transform columns F into gmem panel columns ----
        for (int t = tid; t < NSEQ * NB; t += 1024) {
            int i = t >> 4, j = t & 15;
            W[(size_t)i * NSEQ + k0 + j] = Ap[i * 17 + j];
        }
        __syncthreads();

        // ---- rank-16 trailing update: W = Whist + F * Wp (panel rows zero-based,
        //      panel columns skipped). Warp-per-row, lane-per-float4-col. ----
        {
            int pc0 = k0 >> 2;
            int w = tid >> 5, l = tid & 31;
            for (int rb = 0; rb < 16; rb++) {
                int i = rb * 32 + w;
                bool prow = (i >= k0 && i < k0 + NB);
                float Fi[NB];
                #pragma unroll
                for (int j = 0; j < NB; j++) Fi[j] = Ap[i * 17 + j];
                float4* Wr = (float4*)(W + (size_t)i * NSEQ);
                #pragma unroll
                for (int q = 0; q < 4; q++) {
                    int ch = l + q * 32;
                    float4 acc = prow ? make_float4(0.f, 0.f, 0.f, 0.f) : Wr[ch];
                    #pragma unroll
                    for (int j = 0; j < NB; j++) {
                        float4 bv = *(const float4*)(Wp + j * NSEQ + (ch << 2));
                        acc.x = fmaf(Fi[j], bv.x, acc.x);
                        acc.y = fmaf(Fi[j], bv.y, acc.y);
                        acc.z = fmaf(Fi[j], bv.z, acc.z);
                        acc.w = fmaf(Fi[j], bv.w, acc.w);
                    }
                    bool pcol = (ch >= pc0 && ch < pc0 + 4);
                    if (!pcol) Wr[ch] = acc;
                }
            }
        }
    }
    __syncthreads();

    // ---- resolve column labels from pivot history ----
    if (tid == 0) {
        g_logdet[b] = sh_ld;
        for (int j = 0; j < NSEQ; j++) s_L[j] = j;
        for (int k = NSEQ - 1; k >= 0; k--) {
            int p = s_piv[k];
            if (p != k) { int t = s_L[k]; s_L[k] = s_L[p]; s_L[p] = t; }
        }
    }
    __syncthreads();
    for (int j = tid; j < NSEQ; j += 1024) g_perm[b * NSEQ + j] = s_L[j];
}

// ---------------- BT[j][i] = Binv[i][j] = C[i][L[j]]; also diag and column 0 ----------------
__global__ void perm_k() {
    int j = blockIdx.x, b = blockIdx.y, i = threadIdx.x;
    const float* C = g_W + (size_t)b * NM;
    int Lj = g_perm[b * NSEQ + j];
    float v = C[(size_t)i * NSEQ + Lj];
    g_BT[(size_t)b * NM + (size_t)j * NSEQ + i] = v;
    if (i == j) g_diagB[b * NSEQ + j] = v;
    if (j == 0) g_rootB[b * NSEQ + i] = v;   // Binv[i][0]
}

// ---------------- marginals Y + fp64 dot(Y, scores) ----------------
__global__ void __launch_bounds__(512) y_k(const int* __restrict__ lengths) {
    int h = blockIdx.x, b = blockIdx.y, m = threadIdx.x;
    int len = lengths[b];
    float c = g_c[b];
    float s = g_scores[(size_t)b * NM + (size_t)h * NSEQ + m];
    float y = 0.f;
    if (h <= len && m >= 1 && m <= len && h != m) {
        float A = expf(s - c);
        float diag = (m >= 2) ? g_diagB[b * NSEQ + (m - 1)] : 0.f;
        float G;
        if (h == 0) G = g_rootB[b * NSEQ + (m - 1)] + diag;
        else        G = diag - ((h >= 2) ? g_BT[(size_t)b * NM + (size_t)(h - 1) * NSEQ + (m - 1)] : 0.f);
        y = A * G;
    }
    g_Y[(size_t)b * NM + (size_t)h * NSEQ + m] = y;

    float v = y * s;
    #pragma unroll
    for (int o = 16; o; o >>= 1) v += __shfl_down_sync(0xffffffffu, v, o);
    __shared__ float ws[16];
    if ((m & 31) == 0) ws[m >> 5] = v;
    __syncthreads();
    if (m < 16) {
        v = ws[m];
        #pragma unroll
        for (int o = 8; o; o >>= 1) v += __shfl_down_sync(0xffffu, v, o);
        if (m == 0) atomicAdd(&g_dotp[b], (double)v);
    }
}

// ---------------- finalize logZ and entr into the output ----------------
__global__ void fin_k(const int* __restrict__ lengths, float* __restrict__ out) {
    int b = threadIdx.x;
    if (b < BB) {
        float logZ = (float)g_logdet[b] + (float)lengths[b] * g_c[b];
        out[(size_t)BB * NM + b] = logZ;                              // logZ block
        out[(size_t)2 * BB * NM + BB + b] = logZ - (float)g_dotp[b];  // entr block
    }
}

extern "C" void kernel_launch(void* const* d_in, const int* in_sizes, int n_in,
                              void* d_out, int out_size) {
    const float* Xh = (const float*)d_in[0];
    const float* Xm = (const float*)d_in[1];
    const int*   lengths = (const int*)d_in[2];
    const float* Wh = (const float*)d_in[3];
    const float* bh = (const float*)d_in[4];
    const float* Wm = (const float*)d_in[5];
    const float* bm = (const float*)d_in[6];
    const float* V  = (const float*)d_in[7];
    float* out = (float*)d_out;

    void* p;
    cudaGetSymbolAddress(&p, g_H0);     float* pH0 = (float*)p;
    cudaGetSymbolAddress(&p, g_M0);     float* pM0 = (float*)p;
    cudaGetSymbolAddress(&p, g_Hb);     float* pHb = (float*)p;
    cudaGetSymbolAddress(&p, g_Mb);     float* pMb = (float*)p;
    cudaGetSymbolAddress(&p, g_T);      float* pT  = (float*)p;
    cudaGetSymbolAddress(&p, g_scores); float* pSc = (float*)p;
    cudaGetSymbolAddress(&p, g_Y);      float* pY  = (float*)p;

    cudaFuncSetAttribute(gjb_k, cudaFuncAttributeMaxDynamicSharedMemorySize, GJ_SMEM);

    dim3 gProj(DH / 64, (BB * NSEQ) / 64, 1);  // (2, 256)

    // projections + relu
    gemm_k<false, true, 1><<<gProj, 256>>>(Xh, Wh, bh, pH0, BB*NSEQ, DH, DIN, DIN, DIN, DH, 0, 0, 0);
    gemm_k<false, true, 1><<<gProj, 256>>>(Xm, Wm, bm, pM0, BB*NSEQ, DH, DIN, DIN, DIN, DH, 0, 0, 0);
    relu_k<<<(HS + 255) / 256, 256>>>(pH0, pHb, HS);
    relu_k<<<(HS + 255) / 256, 256>>>(pM0, pMb, HS);

    for (int it = 0; it < NITER; it++) {
        float* H = pHb + (size_t)(it & 1) * HS;
        float* M = pMb + (size_t)(it & 1) * HS;
        // T = H @ V  (flattened over batch)
        gemm_k<false, false, 0><<<gProj, 256>>>(H, V, nullptr, pT, BB*NSEQ, DH, DH, DH, DH, DH, 0, 0, 0);
        // scores = T @ M^T  (batched)
        gemm_k<false, true, 0><<<dim3(8, 8, BB), 256>>>(pT, M, nullptr, pSc, NSEQ, NSEQ, DH,
                                                        DH, DH, NSEQ, (long)NSEQ*DH, (long)NSEQ*DH, (long)NM);
        cmax_k<<<BB, 1024>>>(lengths);
        colsum_k<<<BB, NSEQ>>>(lengths);
        lhat_k<<<dim3(NSEQ, BB), NSEQ>>>(lengths);
        gjb_k<<<BB, 1024, GJ_SMEM>>>();
        perm_k<<<dim3(NSEQ, BB), NSEQ>>>();
        y_k<<<dim3(NSEQ, BB), NSEQ>>>(lengths);

        if (it < NITER - 1) {
            float* Hn = pHb + (size_t)((it + 1) & 1) * HS;
            float* Mn = pMb + (size_t)((it + 1) & 1) * HS;
            // T = Y @ M  (batched)
            gemm_k<false, false, 0><<<dim3(2, 8, BB), 256>>>(pY, M, nullptr, pT, NSEQ, DH, NSEQ,
                                                             NSEQ, DH, DH, (long)NM, (long)NSEQ*DH, (long)NSEQ*DH);
            // Hn = relu(H0 + T @ V^T)
            gemm_k<false, true, 2><<<gProj, 256>>>(pT, V, pH0, Hn, BB*NSEQ, DH, DH, DH, DH, DH, 0, 0, 0);
            // T = Y^T @ H  (batched)
            gemm_k<true, false, 0><<<dim3(2, 8, BB), 256>>>(pY, H, nullptr, pT, NSEQ, DH, NSEQ,
                                                            NSEQ, DH, DH, (long)NM, (long)NSEQ*DH, (long)NSEQ*DH);
            // Mn = relu(M0 + T @ V)
            gemm_k<false, false, 2><<<gProj, 256>>>(pT, V, pM0, Mn, BB*NSEQ, DH, DH, DH, DH, DH, 0, 0, 0);
        }
    }

    fin_k<<<1, BB>>>(lengths, out);
    cudaMemcpyAsync(out, pSc, (size_t)BB * NM * sizeof(float), cudaMemcpyDeviceToDevice, 0);
    cudaMemcpyAsync(out + (size_t)BB * NM + BB, pY, (size_t)BB * NM * sizeof(float), cudaMemcpyDeviceToDevice, 0);
}

// round 6
// speedup vs baseline: 6.2063x; 2.3574x over previous
#include <cuda_runtime.h>
#include <math.h>

#define BB   32
#define NSEQ 512
#define DIN  256
#define DH   128
#define NITER 10
#define NM   (NSEQ*NSEQ)
#define HS   (BB*NSEQ*DH)
#define NB   16

// ---------------- device scratch (no runtime allocation) ----------------
static __device__ float  g_H0[HS];
static __device__ float  g_M0[HS];
static __device__ float  g_Hb[2*HS];
static __device__ float  g_Mb[2*HS];
static __device__ float  g_T[HS];
static __device__ float  g_scores[BB*NM];
static __device__ float  g_W[BB*NM];      // Lhat -> in-place GJ result (cols scrambled)
static __device__ float  g_BT[BB*NM];     // BT[j][i] = Binv[i][j]
static __device__ float  g_Y[BB*NM];
static __device__ float  g_F[BB*NSEQ*NB]; // panel transform, row-major [512][16]
static __device__ float  g_Wp[BB*NB*NSEQ];// swapped panel rows [16][512]
static __device__ float  g_c[BB];
static __device__ float  g_S[BB*NSEQ];
static __device__ double g_logdet[BB];
static __device__ double g_dotp[BB];
static __device__ float  g_diagB[BB*NSEQ];
static __device__ float  g_rootB[BB*NSEQ];
static __device__ int    g_piv[BB*NSEQ];
static __device__ int    g_perm[BB*NSEQ]; // Linv labels

// ---------------- generic tiled GEMM: C[bz] = opA @ opB (+ epilogue) ----------------
template<bool TA, bool TB, int EPI>
__global__ void __launch_bounds__(256) gemm_k(
    const float* __restrict__ A, const float* __restrict__ B,
    const float* __restrict__ C0, float* __restrict__ C,
    int M, int N, int K, int lda, int ldb, int ldc,
    long sA, long sB, long sC)
{
    int bz = blockIdx.z;
    A += (long)bz * sA;  B += (long)bz * sB;  C += (long)bz * sC;

    __shared__ float As[16][64];
    __shared__ float Bs[16][64];

    int tid = threadIdx.x;
    int i0 = blockIdx.y * 64, j0 = blockIdx.x * 64;
    int tx = tid & 15, ty = tid >> 4;

    float acc[4][4] = {};

    for (int k0 = 0; k0 < K; k0 += 16) {
        if (!TA) {
            int i = tid >> 2, kk = (tid & 3) << 2;
            float4 v = *(const float4*)(A + (long)(i0 + i) * lda + k0 + kk);
            As[kk + 0][i] = v.x; As[kk + 1][i] = v.y; As[kk + 2][i] = v.z; As[kk + 3][i] = v.w;
        } else {
            int kk = tid >> 4, i4 = (tid & 15) << 2;
            float4 v = *(const float4*)(A + (long)(k0 + kk) * lda + i0 + i4);
            *(float4*)&As[kk][i4] = v;
        }
        if (!TB) {
            int kk = tid >> 4, j4 = (tid & 15) << 2;
            float4 v = *(const float4*)(B + (long)(k0 + kk) * ldb + j0 + j4);
            *(float4*)&Bs[kk][j4] = v;
        } else {
            int j = tid >> 2, kk = (tid & 3) << 2;
            float4 v = *(const float4*)(B + (long)(j0 + j) * ldb + k0 + kk);
            Bs[kk + 0][j] = v.x; Bs[kk + 1][j] = v.y; Bs[kk + 2][j] = v.z; Bs[kk + 3][j] = v.w;
        }
        __syncthreads();
        #pragma unroll
        for (int kk = 0; kk < 16; kk++) {
            float4 av = *(const float4*)&As[kk][ty << 2];
            float4 bv = *(const float4*)&Bs[kk][tx << 2];
            float ar[4] = {av.x, av.y, av.z, av.w};
            float br[4] = {bv.x, bv.y, bv.z, bv.w};
            #pragma unroll
            for (int a = 0; a < 4; a++)
                #pragma unroll
                for (int q = 0; q < 4; q++)
                    acc[a][q] = fmaf(ar[a], br[q], acc[a][q]);
        }
        __syncthreads();
    }

    #pragma unroll
    for (int a = 0; a < 4; a++) {
        int row = i0 + (ty << 2) + a;
        long off = (long)row * ldc + j0 + (tx << 2);
        float4 r = make_float4(acc[a][0], acc[a][1], acc[a][2], acc[a][3]);
        if (EPI == 1) {
            float4 bb = *(const float4*)(C0 + j0 + (tx << 2));
            r.x += bb.x; r.y += bb.y; r.z += bb.z; r.w += bb.w;
        }
        if (EPI == 2) {
            float4 cv = *(const float4*)(C0 + off);
            r.x = fmaxf(cv.x + r.x, 0.f); r.y = fmaxf(cv.y + r.y, 0.f);
            r.z = fmaxf(cv.z + r.z, 0.f); r.w = fmaxf(cv.w + r.w, 0.f);
        }
        *(float4*)(C + off) = r;
    }
}

__global__ void relu_k(const float* __restrict__ s, float* __restrict__ d, int n) {
    int i = blockIdx.x * blockDim.x + threadIdx.x;
    if (i < n) d[i] = fmaxf(s[i], 0.f);
}

// ---------------- c[b] = max over pair-masked scores; zero dot accumulator ----------------
__global__ void __launch_bounds__(1024) cmax_k(const int* __restrict__ lengths) {
    int b = blockIdx.x, len = lengths[b];
    const float* s = g_scores + (size_t)b * NM;
    float best = -1e30f;
    for (int idx = threadIdx.x; idx < NM; idx += 1024) {
        int h = idx >> 9, m = idx & 511;
        if (h <= len && m >= 1 && m <= len && h != m) {
            float v = s[idx];
            if (v > best) best = v;
        }
    }
    __shared__ float sr[1024];
    sr[threadIdx.x] = best; __syncthreads();
    for (int o = 512; o; o >>= 1) {
        if (threadIdx.x < o) { float v = sr[threadIdx.x + o]; if (v > sr[threadIdx.x]) sr[threadIdx.x] = v; }
        __syncthreads();
    }
    if (threadIdx.x == 0) { g_c[b] = sr[0]; g_dotp[b] = 0.0; }
}

// ---------------- colsum[j] = sum_{h=1..len, h!=m} exp(s[h,m]-c), m=j+1 ----------------
__global__ void colsum_k(const int* __restrict__ lengths) {
    int b = blockIdx.x, j = threadIdx.x, m = j + 1, len = lengths[b];
    float c = g_c[b], s = 0.f;
    if (m < NSEQ && m <= len) {
        const float* sc = g_scores + (size_t)b * NM;
        for (int h = 1; h <= len; h++)
            if (h != m) s += expf(sc[h * NSEQ + m] - c);
    }
    g_S[b * NSEQ + j] = s;
}

// ---------------- build padded 512x512 Lhat ----------------
__global__ void lhat_k(const int* __restrict__ lengths) {
    int i = blockIdx.x, b = blockIdx.y, j = threadIdx.x, len = lengths[b];
    float c = g_c[b];
    const float* sc = g_scores + (size_t)b * NM;
    float v;
    if (i == NSEQ - 1)      v = (j == NSEQ - 1) ? 1.f : 0.f;
    else if (j == NSEQ - 1) v = 0.f;
    else if (i == 0) { int m = j + 1; v = (m <= len) ? expf(sc[m] - c) : 0.f; }
    else if (j == i) {
        int m = i + 1;
        float r = (m <= len) ? expf(sc[m] - c) : 0.f;
        v = r + g_S[b * NSEQ + i] + ((m <= len) ? 0.f : 1.f);
    } else {
        int h = i + 1, m = j + 1;
        v = (h <= len && m <= len) ? -expf(sc[h * NSEQ + m] - c) : 0.f;
    }
    g_W[(size_t)b * NM + (size_t)i * NSEQ + j] = v;
}

// ---------------- panel factor: 512x16 panel, one row per thread, in registers ----------------
__global__ void __launch_bounds__(512) panel_k(int k0) {
    int b = blockIdx.x, tid = threadIdx.x;
    float* W = g_W + (size_t)b * NM;
    float a[NB];
    {
        const float4* src = (const float4*)(W + (size_t)tid * NSEQ + k0);
        #pragma unroll
        for (int q = 0; q < 4; q++) {
            float4 v = src[q];
            a[4*q] = v.x; a[4*q+1] = v.y; a[4*q+2] = v.z; a[4*q+3] = v.w;
        }
    }
    __shared__ float s_tmpK[NB], s_tmpP[NB];
    __shared__ float red_v[16]; __shared__ int red_i[16];
    __shared__ int sh_p;
    __shared__ int s_pivloc[NB];
    __shared__ double sh_ld;
    if (tid == 0) sh_ld = (k0 == 0) ? 0.0 : g_logdet[b];

    #pragma unroll
    for (int j = 0; j < NB; j++) {
        int k = k0 + j;
        // argmax |a[j]| over rows >= k
        float best = (tid >= k) ? fabsf(a[j]) : -1.f;
        int bi = tid;
        #pragma unroll
        for (int o = 16; o; o >>= 1) {
            float ov = __shfl_down_sync(0xffffffffu, best, o);
            int   oi = __shfl_down_sync(0xffffffffu, bi, o);
            if (ov > best) { best = ov; bi = oi; }
        }
        if ((tid & 31) == 0) { red_v[tid >> 5] = best; red_i[tid >> 5] = bi; }
        __syncthreads();
        if (tid < 32) {
            best = (tid < 16) ? red_v[tid] : -2.f;
            bi   = (tid < 16) ? red_i[tid] : 0;
            #pragma unroll
            for (int o = 8; o; o >>= 1) {
                float ov = __shfl_down_sync(0xffffffffu, best, o);
                int   oi = __shfl_down_sync(0xffffffffu, bi, o);
                if (ov > best) { best = ov; bi = oi; }
            }
            if (tid == 0) { sh_p = bi; s_pivloc[j] = bi; }
        }
        __syncthreads();
        int p = sh_p;
        // exchange rows k,p through smem
        if (tid == k) {
            for (int jj = 0; jj < NB; jj++) s_tmpK[jj] = a[jj];
        }
        if (tid == p) {
            for (int jj = 0; jj < NB; jj++) s_tmpP[jj] = a[jj];
        }
        __syncthreads();
        const float* prow = (p != k) ? s_tmpP : s_tmpK;
        if (p != k) {
            if (tid == k) {
                for (int jj = 0; jj < NB; jj++) a[jj] = s_tmpP[jj];
            }
            if (tid == p) {
                for (int jj = 0; jj < NB; jj++) a[jj] = s_tmpK[jj];
            }
        }
        float piv = prow[j];
        float pivinv = 1.f / piv;
        if (tid == 0) sh_ld += log(fabs((double)piv));
        if (tid == k) {
            #pragma unroll
            for (int jj = 0; jj < NB; jj++) a[jj] = (jj == j) ? pivinv : prow[jj] * pivinv;
        } else {
            float cm = a[j];
            #pragma unroll
            for (int jj = 0; jj < NB; jj++)
                if (jj != j) a[jj] = fmaf(-cm, prow[jj] * pivinv, a[jj]);
            a[j] = -cm * pivinv;
        }
        __syncthreads();
    }

    // write F (coalesced)
    {
        float4* fd = (float4*)(g_F + ((size_t)b * NSEQ + tid) * NB);
        #pragma unroll
        for (int q = 0; q < 4; q++)
            fd[q] = make_float4(a[4*q], a[4*q+1], a[4*q+2], a[4*q+3]);
    }
    // apply the 16 row swaps to gmem W in order (512 threads, one float per thread)
    for (int j = 0; j < NB; j++) {
        int k = k0 + j, p = s_pivloc[j];
        if (p != k) {
            float t1 = W[(size_t)k * NSEQ + tid];
            W[(size_t)k * NSEQ + tid] = W[(size_t)p * NSEQ + tid];
            W[(size_t)p * NSEQ + tid] = t1;
        }
        __syncthreads();
    }
    // copy swapped panel rows to g_Wp (coalesced)
    for (int t = tid; t < NB * NSEQ; t += 512) {
        int r = t >> 9, c4 = t & 511;
        g_Wp[(size_t)b * NB * NSEQ + t] = W[(size_t)(k0 + r) * NSEQ + c4];
    }
    // write F into panel columns of W
    {
        float4* wd = (float4*)(W + (size_t)tid * NSEQ + k0);
        #pragma unroll
        for (int q = 0; q < 4; q++)
            wd[q] = make_float4(a[4*q], a[4*q+1], a[4*q+2], a[4*q+3]);
    }
    if (tid < NB) g_piv[b * NSEQ + k0 + tid] = s_pivloc[tid];
    if (tid == 0) g_logdet[b] = sh_ld;
}

// ---------------- rank-16 trailing update: W = base + F*Wp, full chip ----------------
__global__ void __launch_bounds__(256) upd_k(int k0) {
    int b = blockIdx.z;
    float* W = g_W + (size_t)b * NM;
    const float* F  = g_F  + (size_t)b * NSEQ * NB;
    const float* Wp = g_Wp + (size_t)b * NB * NSEQ;
    __shared__ float Fs[NB][64];
    __shared__ float Bs[NB][64];
    int tid = threadIdx.x;
    int i0 = blockIdx.y * 64, j0 = blockIdx.x * 64;
    {
        int i = tid >> 2, kk = (tid & 3) << 2;
        float4 v = *(const float4*)(F + (size_t)(i0 + i) * NB + kk);
        Fs[kk][i] = v.x; Fs[kk+1][i] = v.y; Fs[kk+2][i] = v.z; Fs[kk+3][i] = v.w;
    }
    {
        int kk = tid >> 4, j4 = (tid & 15) << 2;
        *(float4*)&Bs[kk][j4] = *(const float4*)(Wp + (size_t)kk * NSEQ + j0 + j4);
    }
    __syncthreads();
    int tx = tid & 15, ty = tid >> 4;
    float acc[4][4] = {};
    #pragma unroll
    for (int kk = 0; kk < NB; kk++) {
        float4 av = *(const float4*)&Fs[kk][ty << 2];
        float4 bv = *(const float4*)&Bs[kk][tx << 2];
        float ar[4] = {av.x, av.y, av.z, av.w};
        float br[4] = {bv.x, bv.y, bv.z, bv.w};
        #pragma unroll
        for (int a = 0; a < 4; a++)
            #pragma unroll
            for (int q = 0; q < 4; q++)
                acc[a][q] = fmaf(ar[a], br[q], acc[a][q]);
    }
    int col = j0 + (tx << 2);
    bool pcol = (col >= k0 && col < k0 + NB);
    if (pcol) return;
    #pragma unroll
    for (int a = 0; a < 4; a++) {
        int row = i0 + (ty << 2) + a;
        bool prow = (row >= k0 && row < k0 + NB);
        float4* wp4 = (float4*)(W + (size_t)row * NSEQ + col);
        float4 r = make_float4(acc[a][0], acc[a][1], acc[a][2], acc[a][3]);
        if (!prow) {
            float4 base = *wp4;
            r.x += base.x; r.y += base.y; r.z += base.z; r.w += base.w;
        }
        *wp4 = r;
    }
}

// ---------------- resolve labels: g_perm = Linv (Linv[L[j]] = j) ----------------
__global__ void __launch_bounds__(512) labels_k() {
    int b = blockIdx.x, tid = threadIdx.x;
    __shared__ int s_L[NSEQ];
    if (tid == 0) {
        for (int j = 0; j < NSEQ; j++) s_L[j] = j;
        for (int k = NSEQ - 1; k >= 0; k--) {
            int p = g_piv[b * NSEQ + k];
            if (p != k) { int t = s_L[k]; s_L[k] = s_L[p]; s_L[p] = t; }
        }
    }
    __syncthreads();
    g_perm[b * NSEQ + s_L[tid]] = tid;
}

// ---------------- coalesced permuted transpose: BT[Linv[j]][i] = C[i][j] ----------------
__global__ void permT_k() {
    int b = blockIdx.z;
    const float* C = g_W + (size_t)b * NM;
    float* BT = g_BT + (size_t)b * NM;
    const int* Linv = g_perm + b * NSEQ;
    __shared__ float sm[32][33];
    int i0 = blockIdx.y * 32, j0 = blockIdx.x * 32;
    int tx = threadIdx.x, ty = threadIdx.y;
    #pragma unroll
    for (int k = 0; k < 4; k++)
        sm[ty + 8*k][tx] = C[(size_t)(i0 + ty + 8*k) * NSEQ + j0 + tx];
    __syncthreads();
    #pragma unroll
    for (int k = 0; k < 4; k++) {
        int j = j0 + ty + 8*k;
        BT[(size_t)Linv[j] * NSEQ + i0 + tx] = sm[tx][ty + 8*k];
    }
}

__global__ void diag_k() {
    int b = blockIdx.x, j = threadIdx.x;
    g_diagB[b * NSEQ + j] = g_BT[(size_t)b * NM + (size_t)j * NSEQ + j];
    g_rootB[b * NSEQ + j] = g_BT[(size_t)b * NM + j];
}

// ---------------- marginals Y + fp64 dot(Y, scores) ----------------
__global__ void __launch_bounds__(512) y_k(const int* __restrict__ lengths) {
    int h = blockIdx.x, b = blockIdx.y, m = threadIdx.x;
    int len = lengths[b];
    float c = g_c[b];
    float s = g_scores[(size_t)b * NM + (size_t)h * NSEQ + m];
    float y = 0.f;
    if (h <= len && m >= 1 && m <= len && h != m) {
        float A = expf(s - c);
        float diag = (m >= 2) ? g_diagB[b * NSEQ + (m - 1)] : 0.f;
        float G;
        if (h == 0) G = g_rootB[b * NSEQ + (m - 1)] + diag;
        else        G = diag - ((h >= 2) ? g_BT[(size_t)b * NM + (size_t)(h - 1) * NSEQ + (m - 1)] : 0.f);
        y = A * G;
    }
    g_Y[(size_t)b * NM + (size_t)h * NSEQ + m] = y;

    float v = y * s;
    #pragma unroll
    for (int o = 16; o; o >>= 1) v += __shfl_down_sync(0xffffffffu, v, o);
    __shared__ float ws[16];
    if ((m & 31) == 0) ws[m >> 5] = v;
    __syncthreads();
    if (m < 16) {
        v = ws[m];
        #pragma unroll
        for (int o = 8; o; o >>= 1) v += __shfl_down_sync(0xffffu, v, o);
        if (m == 0) atomicAdd(&g_dotp[b], (double)v);
    }
}

__global__ void fin_k(const int* __restrict__ lengths, float* __restrict__ out) {
    int b = threadIdx.x;
    if (b < BB) {
        float logZ = (float)g_logdet[b] + (float)lengths[b] * g_c[b];
        out[(size_t)BB * NM + b] = logZ;
        out[(size_t)2 * BB * NM + BB + b] = logZ - (float)g_dotp[b];
    }
}

extern "C" void kernel_launch(void* const* d_in, const int* in_sizes, int n_in,
                              void* d_out, int out_size) {
    const float* Xh = (const float*)d_in[0];
    const float* Xm = (const float*)d_in[1];
    const int*   lengths = (const int*)d_in[2];
    const float* Wh = (const float*)d_in[3];
    const float* bh = (const float*)d_in[4];
    const float* Wm = (const float*)d_in[5];
    const float* bm = (const float*)d_in[6];
    const float* V  = (const float*)d_in[7];
    float* out = (float*)d_out;

    void* p;
    cudaGetSymbolAddress(&p, g_H0);     float* pH0 = (float*)p;
    cudaGetSymbolAddress(&p, g_M0);     float* pM0 = (float*)p;
    cudaGetSymbolAddress(&p, g_Hb);     float* pHb = (float*)p;
    cudaGetSymbolAddress(&p, g_Mb);     float* pMb = (float*)p;
    cudaGetSymbolAddress(&p, g_T);      float* pT  = (float*)p;
    cudaGetSymbolAddress(&p, g_scores); float* pSc = (float*)p;
    cudaGetSymbolAddress(&p, g_Y);      float* pY  = (float*)p;

    dim3 gProj(DH / 64, (BB * NSEQ) / 64, 1);

    gemm_k<false, true, 1><<<gProj, 256>>>(Xh, Wh, bh, pH0, BB*NSEQ, DH, DIN, DIN, DIN, DH, 0, 0, 0);
    gemm_k<false, true, 1><<<gProj, 256>>>(Xm, Wm, bm, pM0, BB*NSEQ, DH, DIN, DIN, DIN, DH, 0, 0, 0);
    relu_k<<<(HS + 255) / 256, 256>>>(pH0, pHb, HS);
    relu_k<<<(HS + 255) / 256, 256>>>(pM0, pMb, HS);

    for (int it = 0; it < NITER; it++) {
        float* H = pHb + (size_t)(it & 1) * HS;
        float* M = pMb + (size_t)(it & 1) * HS;
        gemm_k<false, false, 0><<<gProj, 256>>>(H, V, nullptr, pT, BB*NSEQ, DH, DH, DH, DH, DH, 0, 0, 0);
        gemm_k<false, true, 0><<<dim3(8, 8, BB), 256>>>(pT, M, nullptr, pSc, NSEQ, NSEQ, DH,
                                                        DH, DH, NSEQ, (long)NSEQ*DH, (long)NSEQ*DH, (long)NM);
        cmax_k<<<BB, 1024>>>(lengths);
        colsum_k<<<BB, NSEQ>>>(lengths);
        lhat_k<<<dim3(NSEQ, BB), NSEQ>>>(lengths);
        for (int k0 = 0; k0 < NSEQ; k0 += NB) {
            panel_k<<<BB, 512>>>(k0);
            upd_k<<<dim3(8, 8, BB), 256>>>(k0);
        }
        labels_k<<<BB, 512>>>();
        permT_k<<<dim3(16, 16, BB), dim3(32, 8)>>>();
        diag_k<<<BB, NSEQ>>>();
        y_k<<<dim3(NSEQ, BB), NSEQ>>>(lengths);

        if (it < NITER - 1) {
            float* Hn = pHb + (size_t)((it + 1) & 1) * HS;
            float* Mn = pMb + (size_t)((it + 1) & 1) * HS;
            gemm_k<false, false, 0><<<dim3(2, 8, BB), 256>>>(pY, M, nullptr, pT, NSEQ, DH, NSEQ,
                                                             NSEQ, DH, DH, (long)NM, (long)NSEQ*DH, (long)NSEQ*DH);
            gemm_k<false, true, 2><<<gProj, 256>>>(pT, V, pH0, Hn, BB*NSEQ, DH, DH, DH, DH, DH, 0, 0, 0);
            gemm_k<true, false, 0><<<dim3(2, 8, BB), 256>>>(pY, H, nullptr, pT, NSEQ, DH, NSEQ,
                                                            NSEQ, DH, DH, (long)NM, (long)NSEQ*DH, (long)NSEQ*DH);
            gemm_k<false, false, 2><<<gProj, 256>>>(pT, V, pM0, Mn, BB*NSEQ, DH, DH, DH, DH, DH, 0, 0, 0);
        }
    }

    fin_k<<<1, BB>>>(lengths, out);
    cudaMemcpyAsync(out, pSc, (size_t)BB * NM * sizeof(float), cudaMemcpyDeviceToDevice, 0);
    cudaMemcpyAsync(out + (size_t)BB * NM + BB, pY, (size_t)BB * NM * sizeof(float), cudaMemcpyDeviceToDevice, 0);
}

// round 8
// speedup vs baseline: 6.5545x; 1.0561x over previous
#include <cuda_runtime.h>
#include <math.h>

#define BB   32
#define NSEQ 512
#define DIN  256
#define DH   128
#define NITER 10
#define NM   (NSEQ*NSEQ)
#define HS   (BB*NSEQ*DH)
#define NB   32

// ---------------- device scratch (no runtime allocation) ----------------
static __device__ float  g_H0[HS];
static __device__ float  g_M0[HS];
static __device__ float  g_Hb[2*HS];
static __device__ float  g_Mb[2*HS];
static __device__ float  g_T[HS];
static __device__ float  g_scores[BB*NM];
static __device__ float  g_W[BB*NM];      // Lhat -> in-place GJ result (cols scrambled)
static __device__ float  g_BT[BB*NM];     // BT[j][i] = Binv[i][j]
static __device__ float  g_Y[BB*NM];
static __device__ float  g_F[BB*NSEQ*NB]; // panel transform, row-major [512][NB]
static __device__ float  g_Wp[BB*NB*NSEQ];// swapped panel rows [NB][512]
static __device__ float  g_c[BB];
static __device__ float  g_S[BB*NSEQ];
static __device__ double g_logdet[BB];
static __device__ double g_dotp[BB];
static __device__ float  g_diagB[BB*NSEQ];
static __device__ float  g_rootB[BB*NSEQ];
static __device__ int    g_piv[BB*NSEQ];
static __device__ int    g_perm[BB*NSEQ]; // Linv labels

// ---------------- generic tiled GEMM: C[bz] = opA @ opB (+ epilogue) ----------------
template<bool TA, bool TB, int EPI>
__global__ void __launch_bounds__(256) gemm_k(
    const float* __restrict__ A, const float* __restrict__ B,
    const float* __restrict__ C0, float* __restrict__ C,
    int M, int N, int K, int lda, int ldb, int ldc,
    long sA, long sB, long sC)
{
    int bz = blockIdx.z;
    A += (long)bz * sA;  B += (long)bz * sB;  C += (long)bz * sC;

    __shared__ float As[16][64];
    __shared__ float Bs[16][64];

    int tid = threadIdx.x;
    int i0 = blockIdx.y * 64, j0 = blockIdx.x * 64;
    int tx = tid & 15, ty = tid >> 4;

    float acc[4][4] = {};

    for (int k0 = 0; k0 < K; k0 += 16) {
        if (!TA) {
            int i = tid >> 2, kk = (tid & 3) << 2;
            float4 v = *(const float4*)(A + (long)(i0 + i) * lda + k0 + kk);
            As[kk + 0][i] = v.x; As[kk + 1][i] = v.y; As[kk + 2][i] = v.z; As[kk + 3][i] = v.w;
        } else {
            int kk = tid >> 4, i4 = (tid & 15) << 2;
            float4 v = *(const float4*)(A + (long)(k0 + kk) * lda + i0 + i4);
            *(float4*)&As[kk][i4] = v;
        }
        if (!TB) {
            int kk = tid >> 4, j4 = (tid & 15) << 2;
            float4 v = *(const float4*)(B + (long)(k0 + kk) * ldb + j0 + j4);
            *(float4*)&Bs[kk][j4] = v;
        } else {
            int j = tid >> 2, kk = (tid & 3) << 2;
            float4 v = *(const float4*)(B + (long)(j0 + j) * ldb + k0 + kk);
            Bs[kk + 0][j] = v.x; Bs[kk + 1][j] = v.y; Bs[kk + 2][j] = v.z; Bs[kk + 3][j] = v.w;
        }
        __syncthreads();
        #pragma unroll
        for (int kk = 0; kk < 16; kk++) {
            float4 av = *(const float4*)&As[kk][ty << 2];
            float4 bv = *(const float4*)&Bs[kk][tx << 2];
            float ar[4] = {av.x, av.y, av.z, av.w};
            float br[4] = {bv.x, bv.y, bv.z, bv.w};
            #pragma unroll
            for (int a = 0; a < 4; a++)
                #pragma unroll
                for (int q = 0; q < 4; q++)
                    acc[a][q] = fmaf(ar[a], br[q], acc[a][q]);
        }
        __syncthreads();
    }

    #pragma unroll
    for (int a = 0; a < 4; a++) {
        int row = i0 + (ty << 2) + a;
        long off = (long)row * ldc + j0 + (tx << 2);
        float4 r = make_float4(acc[a][0], acc[a][1], acc[a][2], acc[a][3]);
        if (EPI == 1) {
            float4 bb = *(const float4*)(C0 + j0 + (tx << 2));
            r.x += bb.x; r.y += bb.y; r.z += bb.z; r.w += bb.w;
        }
        if (EPI == 2) {
            float4 cv = *(const float4*)(C0 + off);
            r.x = fmaxf(cv.x + r.x, 0.f); r.y = fmaxf(cv.y + r.y, 0.f);
            r.z = fmaxf(cv.z + r.z, 0.f); r.w = fmaxf(cv.w + r.w, 0.f);
        }
        *(float4*)(C + off) = r;
    }
}

__global__ void relu_k(const float* __restrict__ s, float* __restrict__ d, int n) {
    int i = blockIdx.x * blockDim.x + threadIdx.x;
    if (i < n) d[i] = fmaxf(s[i], 0.f);
}

// ---------------- c[b] = max over pair-masked scores; zero dot accumulator ----------------
__global__ void __launch_bounds__(1024) cmax_k(const int* __restrict__ lengths) {
    int b = blockIdx.x, len = lengths[b];
    const float* s = g_scores + (size_t)b * NM;
    float best = -1e30f;
    for (int idx = threadIdx.x; idx < NM; idx += 1024) {
        int h = idx >> 9, m = idx & 511;
        if (h <= len && m >= 1 && m <= len && h != m) {
            float v = s[idx];
            if (v > best) best = v;
        }
    }
    __shared__ float sr[1024];
    sr[threadIdx.x] = best; __syncthreads();
    for (int o = 512; o; o >>= 1) {
        if (threadIdx.x < o) { float v = sr[threadIdx.x + o]; if (v > sr[threadIdx.x]) sr[threadIdx.x] = v; }
        __syncthreads();
    }
    if (threadIdx.x == 0) { g_c[b] = sr[0]; g_dotp[b] = 0.0; }
}

// ---------------- colsum[j] = sum_{h=1..len, h!=m} exp(s[h,m]-c), m=j+1 ----------------
__global__ void colsum_k(const int* __restrict__ lengths) {
    int b = blockIdx.x, j = threadIdx.x, m = j + 1, len = lengths[b];
    float c = g_c[b], s = 0.f;
    if (m < NSEQ && m <= len) {
        const float* sc = g_scores + (size_t)b * NM;
        for (int h = 1; h <= len; h++)
            if (h != m) s += expf(sc[h * NSEQ + m] - c);
    }
    g_S[b * NSEQ + j] = s;
}

// ---------------- build padded 512x512 Lhat ----------------
__global__ void lhat_k(const int* __restrict__ lengths) {
    int i = blockIdx.x, b = blockIdx.y, j = threadIdx.x, len = lengths[b];
    float c = g_c[b];
    const float* sc = g_scores + (size_t)b * NM;
    float v;
    if (i == NSEQ - 1)      v = (j == NSEQ - 1) ? 1.f : 0.f;
    else if (j == NSEQ - 1) v = 0.f;
    else if (i == 0) { int m = j + 1; v = (m <= len) ? expf(sc[m] - c) : 0.f; }
    else if (j == i) {
        int m = i + 1;
        float r = (m <= len) ? expf(sc[m] - c) : 0.f;
        v = r + g_S[b * NSEQ + i] + ((m <= len) ? 0.f : 1.f);
    } else {
        int h = i + 1, m = j + 1;
        v = (h <= len && m <= len) ? -expf(sc[h * NSEQ + m] - c) : 0.f;
    }
    g_W[(size_t)b * NM + (size_t)i * NSEQ + j] = v;
}

// ---------------- panel factor: 512xNB panel, one row per thread, in registers ----------------
__global__ void __launch_bounds__(512) panel_k(int k0) {
    int b = blockIdx.x, tid = threadIdx.x;
    float* W = g_W + (size_t)b * NM;
    float a[NB];
    {
        const float4* src = (const float4*)(W + (size_t)tid * NSEQ + k0);
        #pragma unroll
        for (int q = 0; q < NB/4; q++) {
            float4 v = src[q];
            a[4*q] = v.x; a[4*q+1] = v.y; a[4*q+2] = v.z; a[4*q+3] = v.w;
        }
    }
    __shared__ float s_tmpK[NB], s_tmpP[NB];
    __shared__ float red_v[16]; __shared__ int red_i[16];
    __shared__ int sh_p;
    __shared__ int s_pivloc[NB];
    __shared__ double sh_ld;
    __shared__ int s_src[NSEQ];
    __shared__ int s_aff[64];
    __shared__ int s_cnt;
    if (tid == 0) { sh_ld = (k0 == 0) ? 0.0 : g_logdet[b]; s_cnt = 0; }
    s_src[tid] = tid;

    #pragma unroll
    for (int j = 0; j < NB; j++) {
        int k = k0 + j;
        // argmax |a[j]| over rows >= k (one row per thread)
        float best = (tid >= k) ? fabsf(a[j]) : -1.f;
        int bi = tid;
        #pragma unroll
        for (int o = 16; o; o >>= 1) {
            float ov = __shfl_down_sync(0xffffffffu, best, o);
            int   oi = __shfl_down_sync(0xffffffffu, bi, o);
            if (ov > best) { best = ov; bi = oi; }
        }
        if ((tid & 31) == 0) { red_v[tid >> 5] = best; red_i[tid >> 5] = bi; }
        __syncthreads();
        if (tid < 32) {
            best = (tid < 16) ? red_v[tid] : -2.f;
            bi   = (tid < 16) ? red_i[tid] : 0;
            #pragma unroll
            for (int o = 8; o; o >>= 1) {
                float ov = __shfl_down_sync(0xffffffffu, best, o);
                int   oi = __shfl_down_sync(0xffffffffu, bi, o);
                if (ov > best) { best = ov; bi = oi; }
            }
            if (tid == 0) { sh_p = bi; s_pivloc[j] = bi; }
        }
        __syncthreads();
        int p = sh_p;
        // exchange register rows k,p through smem
        if (tid == k) {
            for (int jj = 0; jj < NB; jj++) s_tmpK[jj] = a[jj];
        }
        if (tid == p) {
            for (int jj = 0; jj < NB; jj++) s_tmpP[jj] = a[jj];
        }
        __syncthreads();
        const float* prow = (p != k) ? s_tmpP : s_tmpK;
        if (p != k) {
            if (tid == k) {
                for (int jj = 0; jj < NB; jj++) a[jj] = s_tmpP[jj];
            }
            if (tid == p) {
                for (int jj = 0; jj < NB; jj++) a[jj] = s_tmpK[jj];
            }
        }
        float piv = prow[j];
        float pivinv = 1.f / piv;
        if (tid == 0) sh_ld += log(fabs((double)piv));
        if (tid == k) {
            #pragma unroll
            for (int jj = 0; jj < NB; jj++) a[jj] = (jj == j) ? pivinv : prow[jj] * pivinv;
        } else {
            float cm = a[j];
            #pragma unroll
            for (int jj = 0; jj < NB; jj++)
                if (jj != j) a[jj] = fmaf(-cm, prow[jj] * pivinv, a[jj]);
            a[j] = -cm * pivinv;
        }
        __syncthreads();
    }

    // write F (coalesced per-thread-contiguous)
    {
        float4* fd = (float4*)(g_F + ((size_t)b * NSEQ + tid) * NB);
        #pragma unroll
        for (int q = 0; q < NB/4; q++)
            fd[q] = make_float4(a[4*q], a[4*q+1], a[4*q+2], a[4*q+3]);
    }

    // ---- batched pivot swaps: simulate permutation, gather affected rows ----
    if (tid == 0) {
        for (int j = 0; j < NB; j++) {
            int k = k0 + j, p = s_pivloc[j];
            if (p != k) { int t = s_src[k]; s_src[k] = s_src[p]; s_src[p] = t; }
        }
    }
    __syncthreads();
    if (s_src[tid] != tid) { int idx = atomicAdd(&s_cnt, 1); s_aff[idx] = tid; }
    __syncthreads();
    int cnt = s_cnt;
    {
        // column-disjoint gather: thread tid owns column tid only
        float buf[64];
        #pragma unroll
        for (int aa = 0; aa < 64; aa++)
            if (aa < cnt) buf[aa] = W[(size_t)s_src[s_aff[aa]] * NSEQ + tid];
        #pragma unroll
        for (int aa = 0; aa < 64; aa++)
            if (aa < cnt) W[(size_t)s_aff[aa] * NSEQ + tid] = buf[aa];
    }
    __syncthreads();

    // copy swapped panel rows to g_Wp (coalesced)
    for (int t = tid; t < NB * NSEQ; t += 512) {
        int r = t >> 9, c4 = t & 511;
        g_Wp[(size_t)b * NB * NSEQ + t] = W[(size_t)(k0 + r) * NSEQ + c4];
    }
    // write F into panel columns of W
    {
        float4* wd = (float4*)(W + (size_t)tid * NSEQ + k0);
        #pragma unroll
        for (int q = 0; q < NB/4; q++)
            wd[q] = make_float4(a[4*q], a[4*q+1], a[4*q+2], a[4*q+3]);
    }
    if (tid < NB) g_piv[b * NSEQ + k0 + tid] = s_pivloc[tid];
    if (tid == 0) g_logdet[b] = sh_ld;
}

// ---------------- rank-NB trailing update: W = base + F*Wp, full chip ----------------
__global__ void __launch_bounds__(256) upd_k(int k0) {
    int b = blockIdx.z;
    float* W = g_W + (size_t)b * NM;
    const float* F  = g_F  + (size_t)b * NSEQ * NB;
    const float* Wp = g_Wp + (size_t)b * NB * NSEQ;
    __shared__ float Fs[NB][64];
    __shared__ float Bs[NB][64];
    int tid = threadIdx.x;
    int i0 = blockIdx.y * 64, j0 = blockIdx.x * 64;
    {
        int i = tid >> 2, kk = (tid & 3) << 3;
        float4 v1 = *(const float4*)(F + (size_t)(i0 + i) * NB + kk);
        float4 v2 = *(const float4*)(F + (size_t)(i0 + i) * NB + kk + 4);
        Fs[kk+0][i] = v1.x; Fs[kk+1][i] = v1.y; Fs[kk+2][i] = v1.z; Fs[kk+3][i] = v1.w;
        Fs[kk+4][i] = v2.x; Fs[kk+5][i] = v2.y; Fs[kk+6][i] = v2.z; Fs[kk+7][i] = v2.w;
    }
    {
        int kk = tid >> 3, j8 = (tid & 7) << 3;
        *(float4*)&Bs[kk][j8]     = *(const float4*)(Wp + (size_t)kk * NSEQ + j0 + j8);
        *(float4*)&Bs[kk][j8 + 4] = *(const float4*)(Wp + (size_t)kk * NSEQ + j0 + j8 + 4);
    }
    __syncthreads();
    int tx = tid & 15, ty = tid >> 4;
    float acc[4][4] = {};
    #pragma unroll
    for (int kk = 0; kk < NB; kk++) {
        float4 av = *(const float4*)&Fs[kk][ty << 2];
        float4 bv = *(const float4*)&Bs[kk][tx << 2];
        float ar[4] = {av.x, av.y, av.z, av.w};
        float br[4] = {bv.x, bv.y, bv.z, bv.w};
        #pragma unroll
        for (int a = 0; a < 4; a++)
            #pragma unroll
            for (int q = 0; q < 4; q++)
                acc[a][q] = fmaf(ar[a], br[q], acc[a][q]);
    }
    int col = j0 + (tx << 2);
    bool pcol = (col >= k0 && col < k0 + NB);
    if (pcol) return;
    #pragma unroll
    for (int a = 0; a < 4; a++) {
        int row = i0 + (ty << 2) + a;
        bool prow = (row >= k0 && row < k0 + NB);
        float4* wp4 = (float4*)(W + (size_t)row * NSEQ + col);
        float4 r = make_float4(acc[a][0], acc[a][1], acc[a][2], acc[a][3]);
        if (!prow) {
            float4 base = *wp4;
            r.x += base.x; r.y += base.y; r.z += base.z; r.w += base.w;
        }
        *wp4 = r;
    }
}

// ---------------- resolve labels: g_perm = Linv (Linv[L[j]] = j) ----------------
__global__ void __launch_bounds__(512) labels_k() {
    int b = blockIdx.x, tid = threadIdx.x;
    __shared__ int s_L[NSEQ];
    if (tid == 0) {
        for (int j = 0; j < NSEQ; j++) s_L[j] = j;
        for (int k = NSEQ - 1; k >= 0; k--) {
            int p = g_piv[b * NSEQ + k];
            if (p != k) { int t = s_L[k]; s_L[k] = s_L[p]; s_L[p] = t; }
        }
    }
    __syncthreads();
    g_perm[b * NSEQ + s_L[tid]] = tid;
}

// ---------------- coalesced permuted transpose: BT[Linv[j]][i] = C[i][j] ----------------
__global__ void permT_k() {
    int b = blockIdx.z;
    const float* C = g_W + (size_t)b * NM;
    float* BT = g_BT + (size_t)b * NM;
    const int* Linv = g_perm + b * NSEQ;
    __shared__ float sm[32][33];
    int i0 = blockIdx.y * 32, j0 = blockIdx.x * 32;
    int tx = threadIdx.x, ty = threadIdx.y;
    #pragma unroll
    for (int k = 0; k < 4; k++)
        sm[ty + 8*k][tx] = C[(size_t)(i0 + ty + 8*k) * NSEQ + j0 + tx];
    __syncthreads();
    #pragma unroll
    for (int k = 0; k < 4; k++) {
        int j = j0 + ty + 8*k;
        BT[(size_t)Linv[j] * NSEQ + i0 + tx] = sm[tx][ty + 8*k];
    }
}

__global__ void diag_k() {
    int b = blockIdx.x, j = threadIdx.x;
    g_diagB[b * NSEQ + j] = g_BT[(size_t)b * NM + (size_t)j * NSEQ + j];
    g_rootB[b * NSEQ + j] = g_BT[(size_t)b * NM + j];
}

// ---------------- marginals Y + fp64 dot(Y, scores) ----------------
__global__ void __launch_bounds__(512) y_k(const int* __restrict__ lengths) {
    int h = blockIdx.x, b = blockIdx.y, m = threadIdx.x;
    int len = lengths[b];
    float c = g_c[b];
    float s = g_scores[(size_t)b * NM + (size_t)h * NSEQ + m];
    float y = 0.f;
    if (h <= len && m >= 1 && m <= len && h != m) {
        float A = expf(s - c);
        float diag = (m >= 2) ? g_diagB[b * NSEQ + (m - 1)] : 0.f;
        float G;
        if (h == 0) G = g_rootB[b * NSEQ + (m - 1)] + diag;
        else        G = diag - ((h >= 2) ? g_BT[(size_t)b * NM + (size_t)(h - 1) * NSEQ + (m - 1)] : 0.f);
        y = A * G;
    }
    g_Y[(size_t)b * NM + (size_t)h * NSEQ + m] = y;

    float v = y * s;
    #pragma unroll
    for (int o = 16; o; o >>= 1) v += __shfl_down_sync(0xffffffffu, v, o);
    __shared__ float ws[16];
    if ((m & 31) == 0) ws[m >> 5] = v;
    __syncthreads();
    if (m < 16) {
        v = ws[m];
        #pragma unroll
        for (int o = 8; o; o >>= 1) v += __shfl_down_sync(0xffffu, v, o);
        if (m == 0) atomicAdd(&g_dotp[b], (double)v);
    }
}

__global__ void fin_k(const int* __restrict__ lengths, float* __restrict__ out) {
    int b = threadIdx.x;
    if (b < BB) {
        float logZ = (float)g_logdet[b] + (float)lengths[b] * g_c[b];
        out[(size_t)BB * NM + b] = logZ;
        out[(size_t)2 * BB * NM + BB + b] = logZ - (float)g_dotp[b];
    }
}

extern "C" void kernel_launch(void* const* d_in, const int* in_sizes, int n_in,
                              void* d_out, int out_size) {
    const float* Xh = (const float*)d_in[0];
    const float* Xm = (const float*)d_in[1];
    const int*   lengths = (const int*)d_in[2];
    const float* Wh = (const float*)d_in[3];
    const float* bh = (const float*)d_in[4];
    const float* Wm = (const float*)d_in[5];
    const float* bm = (const float*)d_in[6];
    const float* V  = (const float*)d_in[7];
    float* out = (float*)d_out;

    void* p;
    cudaGetSymbolAddress(&p, g_H0);     float* pH0 = (float*)p;
    cudaGetSymbolAddress(&p, g_M0);     float* pM0 = (float*)p;
    cudaGetSymbolAddress(&p, g_Hb);     float* pHb = (float*)p;
    cudaGetSymbolAddress(&p, g_Mb);     float* pMb = (float*)p;
    cudaGetSymbolAddress(&p, g_T);      float* pT  = (float*)p;
    cudaGetSymbolAddress(&p, g_scores); float* pSc = (float*)p;
    cudaGetSymbolAddress(&p, g_Y);      float* pY  = (float*)p;

    dim3 gProj(DH / 64, (BB * NSEQ) / 64, 1);

    gemm_k<false, true, 1><<<gProj, 256>>>(Xh, Wh, bh, pH0, BB*NSEQ, DH, DIN, DIN, DIN, DH, 0, 0, 0);
    gemm_k<false, true, 1><<<gProj, 256>>>(Xm, Wm, bm, pM0, BB*NSEQ, DH, DIN, DIN, DIN, DH, 0, 0, 0);
    relu_k<<<(HS + 255) / 256, 256>>>(pH0, pHb, HS);
    relu_k<<<(HS + 255) / 256, 256>>>(pM0, pMb, HS);

    for (int it = 0; it < NITER; it++) {
        float* H = pHb + (size_t)(it & 1) * HS;
        float* M = pMb + (size_t)(it & 1) * HS;
        gemm_k<false, false, 0><<<gProj, 256>>>(H, V, nullptr, pT, BB*NSEQ, DH, DH, DH, DH, DH, 0, 0, 0);
        gemm_k<false, true, 0><<<dim3(8, 8, BB), 256>>>(pT, M, nullptr, pSc, NSEQ, NSEQ, DH,
                                                        DH, DH, NSEQ, (long)NSEQ*DH, (long)NSEQ*DH, (long)NM);
        cmax_k<<<BB, 1024>>>(lengths);
        colsum_k<<<BB, NSEQ>>>(lengths);
        lhat_k<<<dim3(NSEQ, BB), NSEQ>>>(lengths);
        for (int k0 = 0; k0 < NSEQ; k0 += NB) {
            panel_k<<<BB, 512>>>(k0);
            upd_k<<<dim3(8, 8, BB), 256>>>(k0);
        }
        labels_k<<<BB, 512>>>();
        permT_k<<<dim3(16, 16, BB), dim3(32, 8)>>>();
        diag_k<<<BB, NSEQ>>>();
        y_k<<<dim3(NSEQ, BB), NSEQ>>>(lengths);

        if (it < NITER - 1) {
            float* Hn = pHb + (size_t)((it + 1) & 1) * HS;
            float* Mn = pMb + (size_t)((it + 1) & 1) * HS;
            gemm_k<false, false, 0><<<dim3(2, 8, BB), 256>>>(pY, M, nullptr, pT, NSEQ, DH, NSEQ,
                                                             NSEQ, DH, DH, (long)NM, (long)NSEQ*DH, (long)NSEQ*DH);
            gemm_k<false, true, 2><<<gProj, 256>>>(pT, V, pH0, Hn, BB*NSEQ, DH, DH, DH, DH, DH, 0, 0, 0);
            gemm_k<true, false, 0><<<dim3(2, 8, BB), 256>>>(pY, H, nullptr, pT, NSEQ, DH, NSEQ,
                                                            NSEQ, DH, DH, (long)NM, (long)NSEQ*DH, (long)NSEQ*DH);
            gemm_k<false, false, 2><<<gProj, 256>>>(pT, V, pM0, Mn, BB*NSEQ, DH, DH, DH, DH, DH, 0, 0, 0);
        }
    }

    fin_k<<<1, BB>>>(lengths, out);
    cudaMemcpyAsync(out, pSc, (size_t)BB * NM * sizeof(float), cudaMemcpyDeviceToDevice, 0);
    cudaMemcpyAsync(out + (size_t)BB * NM + BB, pY, (size_t)BB * NM * sizeof(float), cudaMemcpyDeviceToDevice, 0);
}

// round 12
// speedup vs baseline: 6.6863x; 1.0201x over previous
#include <cuda_runtime.h>
#include <math.h>

#define BB   32
#define NSEQ 512
#define DIN  256
#define DH   128
#define NITER 10
#define NM   (NSEQ*NSEQ)
#define HS   (BB*NSEQ*DH)
#define NB   32

// ---------------- device scratch (no runtime allocation) ----------------
static __device__ float  g_H0[HS];
static __device__ float  g_M0[HS];
static __device__ float  g_Hb[2*HS];
static __device__ float  g_Mb[2*HS];
static __device__ float  g_T[HS];
static __device__ float  g_scores[BB*NM];
static __device__ float  g_W[BB*NM];      // Lhat -> in-place GJ result (cols scrambled)
static __device__ float  g_BT[BB*NM];     // BT[j][i] = Binv[i][j]
static __device__ float  g_Y[BB*NM];
static __device__ float  g_F[BB*NSEQ*NB]; // panel transform, row-major [512][NB]
static __device__ float  g_Wp[BB*NB*NSEQ];// swapped panel rows [NB][512]
static __device__ unsigned g_cbits[BB];   // order-encoded max
static __device__ float  g_S[BB*NSEQ];
static __device__ double g_logdet[BB];
static __device__ double g_dotp[BB];
static __device__ float  g_diagB[BB*NSEQ];
static __device__ int    g_piv[BB*NSEQ];
static __device__ int    g_perm[BB*NSEQ]; // Linv labels

__device__ __forceinline__ unsigned enc_f(float v) {
    unsigned u = __float_as_uint(v);
    return (u & 0x80000000u) ? ~u : (u | 0x80000000u);
}
__device__ __forceinline__ float dec_f(unsigned k) {
    return (k & 0x80000000u) ? __uint_as_float(k & 0x7fffffffu) : __uint_as_float(~k);
}

// ---------------- 64x64 GEMM (startup projections) ----------------
template<bool TA, bool TB, int EPI>
__global__ void __launch_bounds__(256) gemm_k(
    const float* __restrict__ A, const float* __restrict__ B,
    const float* __restrict__ C0, float* __restrict__ C,
    int M, int N, int K, int lda, int ldb, int ldc,
    long sA, long sB, long sC)
{
    int bz = blockIdx.z;
    A += (long)bz * sA;  B += (long)bz * sB;  C += (long)bz * sC;
    __shared__ float As[16][64];
    __shared__ float Bs[16][64];
    int tid = threadIdx.x;
    int i0 = blockIdx.y * 64, j0 = blockIdx.x * 64;
    int tx = tid & 15, ty = tid >> 4;
    float acc[4][4] = {};
    for (int k0 = 0; k0 < K; k0 += 16) {
        if (!TA) {
            int i = tid >> 2, kk = (tid & 3) << 2;
            float4 v = *(const float4*)(A + (long)(i0 + i) * lda + k0 + kk);
            As[kk + 0][i] = v.x; As[kk + 1][i] = v.y; As[kk + 2][i] = v.z; As[kk + 3][i] = v.w;
        } else {
            int kk = tid >> 4, i4 = (tid & 15) << 2;
            float4 v = *(const float4*)(A + (long)(k0 + kk) * lda + i0 + i4);
            *(float4*)&As[kk][i4] = v;
        }
        if (!TB) {
            int kk = tid >> 4, j4 = (tid & 15) << 2;
            float4 v = *(const float4*)(B + (long)(k0 + kk) * ldb + j0 + j4);
            *(float4*)&Bs[kk][j4] = v;
        } else {
            int j = tid >> 2, kk = (tid & 3) << 2;
            float4 v = *(const float4*)(B + (long)(j0 + j) * ldb + k0 + kk);
            Bs[kk + 0][j] = v.x; Bs[kk + 1][j] = v.y; Bs[kk + 2][j] = v.z; Bs[kk + 3][j] = v.w;
        }
        __syncthreads();
        #pragma unroll
        for (int kk = 0; kk < 16; kk++) {
            float4 av = *(const float4*)&As[kk][ty << 2];
            float4 bv = *(const float4*)&Bs[kk][tx << 2];
            float ar[4] = {av.x, av.y, av.z, av.w};
            float br[4] = {bv.x, bv.y, bv.z, bv.w};
            #pragma unroll
            for (int a = 0; a < 4; a++)
                #pragma unroll
                for (int q = 0; q < 4; q++)
                    acc[a][q] = fmaf(ar[a], br[q], acc[a][q]);
        }
        __syncthreads();
    }
    #pragma unroll
    for (int a = 0; a < 4; a++) {
        int row = i0 + (ty << 2) + a;
        long off = (long)row * ldc + j0 + (tx << 2);
        float4 r = make_float4(acc[a][0], acc[a][1], acc[a][2], acc[a][3]);
        if (EPI == 1) {
            float4 bb = *(const float4*)(C0 + j0 + (tx << 2));
            r.x += bb.x; r.y += bb.y; r.z += bb.z; r.w += bb.w;
        }
        *(float4*)(C + off) = r;
    }
}

// ---------------- 128x64 GEMM, 8x4 micro; EPI: 0 plain, 2 relu(C0+acc), 3 store+masked-atomic-max ----------------
template<bool TA, bool TB, int EPI>
__global__ void __launch_bounds__(256) gemm128_k(
    const float* __restrict__ A, const float* __restrict__ B,
    const float* __restrict__ C0, float* __restrict__ C,
    int K, int lda, int ldb, int ldc,
    long sA, long sB, long sC,
    const int* __restrict__ lengths)
{
    int bz = blockIdx.z;
    A += (long)bz * sA;  B += (long)bz * sB;  C += (long)bz * sC;
    __shared__ float As[16][128];
    __shared__ float Bs[16][64];
    int tid = threadIdx.x;
    int i0 = blockIdx.y * 128, j0 = blockIdx.x * 64;
    int ty = tid >> 4, tx = tid & 15;
    float acc[8][4] = {};
    for (int k0 = 0; k0 < K; k0 += 16) {
        if (!TA) {
            int i = tid >> 1, kb = (tid & 1) << 3;
            float4 v1 = *(const float4*)(A + (long)(i0 + i) * lda + k0 + kb);
            float4 v2 = *(const float4*)(A + (long)(i0 + i) * lda + k0 + kb + 4);
            As[kb+0][i] = v1.x; As[kb+1][i] = v1.y; As[kb+2][i] = v1.z; As[kb+3][i] = v1.w;
            As[kb+4][i] = v2.x; As[kb+5][i] = v2.y; As[kb+6][i] = v2.z; As[kb+7][i] = v2.w;
        } else {
            int kk = tid >> 4, i8 = (tid & 15) << 3;
            float4 v1 = *(const float4*)(A + (long)(k0 + kk) * lda + i0 + i8);
            float4 v2 = *(const float4*)(A + (long)(k0 + kk) * lda + i0 + i8 + 4);
            *(float4*)&As[kk][i8] = v1;
            *(float4*)&As[kk][i8 + 4] = v2;
        }
        if (!TB) {
            int kk = tid >> 4, j4 = (tid & 15) << 2;
            *(float4*)&Bs[kk][j4] = *(const float4*)(B + (long)(k0 + kk) * ldb + j0 + j4);
        } else {
            int j = tid >> 2, kk = (tid & 3) << 2;
            float4 v = *(const float4*)(B + (long)(j0 + j) * ldb + k0 + kk);
            Bs[kk+0][j] = v.x; Bs[kk+1][j] = v.y; Bs[kk+2][j] = v.z; Bs[kk+3][j] = v.w;
        }
        __syncthreads();
        #pragma unroll
        for (int kk = 0; kk < 16; kk++) {
            float4 a1 = *(const float4*)&As[kk][ty << 3];
            float4 a2 = *(const float4*)&As[kk][(ty << 3) + 4];
            float4 bv = *(const float4*)&Bs[kk][tx << 2];
            float ar[8] = {a1.x, a1.y, a1.z, a1.w, a2.x, a2.y, a2.z, a2.w};
            float br[4] = {bv.x, bv.y, bv.z, bv.w};
            #pragma unroll
            for (int a = 0; a < 8; a++)
                #pragma unroll
                for (int q = 0; q < 4; q++)
                    acc[a][q] = fmaf(ar[a], br[q], acc[a][q]);
        }
        __syncthreads();
    }
    int colb = j0 + (tx << 2);
    #pragma unroll
    for (int a = 0; a < 8; a++) {
        int row = i0 + (ty << 3) + a;
        long off = (long)row * ldc + colb;
        float4 r = make_float4(acc[a][0], acc[a][1], acc[a][2], acc[a][3]);
        if (EPI == 2) {
            float4 cv = *(const float4*)(C0 + off);
            r.x = fmaxf(cv.x + r.x, 0.f); r.y = fmaxf(cv.y + r.y, 0.f);
            r.z = fmaxf(cv.z + r.z, 0.f); r.w = fmaxf(cv.w + r.w, 0.f);
        }
        *(float4*)(C + off) = r;
    }
    if (EPI == 3) {
        int len = lengths[bz];
        unsigned key = 0u;
        #pragma unroll
        for (int a = 0; a < 8; a++) {
            int h = i0 + (ty << 3) + a;
            #pragma unroll
            for (int q = 0; q < 4; q++) {
                int m = colb + q;
                if (h <= len && m >= 1 && m <= len && h != m) {
                    unsigned k2 = enc_f(acc[a][q]);
                    if (k2 > key) key = k2;
                }
            }
        }
        #pragma unroll
        for (int o = 16; o; o >>= 1) {
            unsigned ok = __shfl_down_sync(0xffffffffu, key, o);
            if (ok > key) key = ok;
        }
        if ((tid & 31) == 0 && key) atomicMax(&g_cbits[bz], key);
    }
}

__global__ void relu_k(const float* __restrict__ s, float* __restrict__ d, int n) {
    int i = blockIdx.x * blockDim.x + threadIdx.x;
    if (i < n) d[i] = fmaxf(s[i], 0.f);
}

__global__ void init_k() {
    int b = threadIdx.x;
    if (b < BB) { g_cbits[b] = 0u; g_dotp[b] = 0.0; }
}

// ---------------- colsum[j] = sum_{h=1..len, h!=m} exp(s[h,m]-c), m=j+1 ----------------
__global__ void colsum_k(const int* __restrict__ lengths) {
    int b = blockIdx.x, j = threadIdx.x, m = j + 1, len = lengths[b];
    float c = dec_f(g_cbits[b]), s = 0.f;
    if (m < NSEQ && m <= len) {
        const float* sc = g_scores + (size_t)b * NM;
        for (int h = 1; h <= len; h++)
            if (h != m) s += expf(sc[h * NSEQ + m] - c);
    }
    g_S[b * NSEQ + j] = s;
}

// ---------------- build padded 512x512 Lhat ----------------
__global__ void lhat_k(const int* __restrict__ lengths) {
    int i = blockIdx.x, b = blockIdx.y, j = threadIdx.x, len = lengths[b];
    float c = dec_f(g_cbits[b]);
    const float* sc = g_scores + (size_t)b * NM;
    float v;
    if (i == NSEQ - 1)      v = (j == NSEQ - 1) ? 1.f : 0.f;
    else if (j == NSEQ - 1) v = 0.f;
    else if (i == 0) { int m = j + 1; v = (m <= len) ? expf(sc[m] - c) : 0.f; }
    else if (j == i) {
        int m = i + 1;
        float r = (m <= len) ? expf(sc[m] - c) : 0.f;
        v = r + g_S[b * NSEQ + i] + ((m <= len) ? 0.f : 1.f);
    } else {
        int h = i + 1, m = j + 1;
        v = (h <= len && m <= len) ? -expf(sc[h * NSEQ + m] - c) : 0.f;
    }
    g_W[(size_t)b * NM + (size_t)i * NSEQ + j] = v;
}

// ---------------- panel factor: 512xNB panel, one row per thread, in registers ----------------
__global__ void __launch_bounds__(512) panel_k(int k0) {
    int b = blockIdx.x, tid = threadIdx.x;
    float* W = g_W + (size_t)b * NM;
    float a[NB];
    {
        const float4* src = (const float4*)(W + (size_t)tid * NSEQ + k0);
        #pragma unroll
        for (int q = 0; q < NB/4; q++) {
            float4 v = src[q];
            a[4*q] = v.x; a[4*q+1] = v.y; a[4*q+2] = v.z; a[4*q+3] = v.w;
        }
    }
    __shared__ float s_tmpK[NB], s_tmpP[NB];
    __shared__ float red_v[16]; __shared__ int red_i[16];
    __shared__ int sh_p;
    __shared__ int s_pivloc[NB];
    __shared__ double sh_ld;
    __shared__ int s_src[NSEQ];
    __shared__ int s_aff[64];
    __shared__ int s_cnt;
    if (tid == 0) { sh_ld = (k0 == 0) ? 0.0 : g_logdet[b]; s_cnt = 0; }
    s_src[tid] = tid;

    #pragma unroll
    for (int j = 0; j < NB; j++) {
        int k = k0 + j;
        float best = (tid >= k) ? fabsf(a[j]) : -1.f;
        int bi = tid;
        #pragma unroll
        for (int o = 16; o; o >>= 1) {
            float ov = __shfl_down_sync(0xffffffffu, best, o);
            int   oi = __shfl_down_sync(0xffffffffu, bi, o);
            if (ov > best) { best = ov; bi = oi; }
        }
        if ((tid & 31) == 0) { red_v[tid >> 5] = best; red_i[tid >> 5] = bi; }
        __syncthreads();
        if (tid < 32) {
            best = (tid < 16) ? red_v[tid] : -2.f;
            bi   = (tid < 16) ? red_i[tid] : 0;
            #pragma unroll
            for (int o = 8; o; o >>= 1) {
                float ov = __shfl_down_sync(0xffffffffu, best, o);
                int   oi = __shfl_down_sync(0xffffffffu, bi, o);
                if (ov > best) { best = ov; bi = oi; }
            }
            if (tid == 0) { sh_p = bi; s_pivloc[j] = bi; }
        }
        __syncthreads();
        int p = sh_p;
        if (tid == k) {
            for (int jj = 0; jj < NB; jj++) s_tmpK[jj] = a[jj];
        }
        if (tid == p) {
            for (int jj = 0; jj < NB; jj++) s_tmpP[jj] = a[jj];
        }
        __syncthreads();
        const float* prow = (p != k) ? s_tmpP : s_tmpK;
        if (p != k) {
            if (tid == k) {
                for (int jj = 0; jj < NB; jj++) a[jj] = s_tmpP[jj];
            }
            if (tid == p) {
                for (int jj = 0; jj < NB; jj++) a[jj] = s_tmpK[jj];
            }
        }
        float piv = prow[j];
        float pivinv = 1.f / piv;
        if (tid == 0) sh_ld += log(fabs((double)piv));
        if (tid == k) {
            #pragma unroll
            for (int jj = 0; jj < NB; jj++) a[jj] = (jj == j) ? pivinv : prow[jj] * pivinv;
        } else {
            float cm = a[j];
            #pragma unroll
            for (int jj = 0; jj < NB; jj++)
                if (jj != j) a[jj] = fmaf(-cm, prow[jj] * pivinv, a[jj]);
            a[j] = -cm * pivinv;
        }
        __syncthreads();
    }

    {
        float4* fd = (float4*)(g_F + ((size_t)b * NSEQ + tid) * NB);
        #pragma unroll
        for (int q = 0; q < NB/4; q++)
            fd[q] = make_float4(a[4*q], a[4*q+1], a[4*q+2], a[4*q+3]);
    }

    if (tid == 0) {
        for (int j = 0; j < NB; j++) {
            int k = k0 + j, p = s_pivloc[j];
            if (p != k) { int t = s_src[k]; s_src[k] = s_src[p]; s_src[p] = t; }
        }
    }
    __syncthreads();
    if (s_src[tid] != tid) { int idx = atomicAdd(&s_cnt, 1); s_aff[idx] = tid; }
    __syncthreads();
    int cnt = s_cnt;
    {
        float buf[64];
        #pragma unroll
        for (int aa = 0; aa < 64; aa++)
            if (aa < cnt) buf[aa] = W[(size_t)s_src[s_aff[aa]] * NSEQ + tid];
        #pragma unroll
        for (int aa = 0; aa < 64; aa++)
            if (aa < cnt) W[(size_t)s_aff[aa] * NSEQ + tid] = buf[aa];
    }
    __syncthreads();

    for (int t = tid; t < NB * NSEQ; t += 512) {
        int r = t >> 9, c4 = t & 511;
        g_Wp[(size_t)b * NB * NSEQ + t] = W[(size_t)(k0 + r) * NSEQ + c4];
    }
    {
        float4* wd = (float4*)(W + (size_t)tid * NSEQ + k0);
        #pragma unroll
        for (int q = 0; q < NB/4; q++)
            wd[q] = make_float4(a[4*q], a[4*q+1], a[4*q+2], a[4*q+3]);
    }
    if (tid < NB) g_piv[b * NSEQ + k0 + tid] = s_pivloc[tid];
    if (tid == 0) g_logdet[b] = sh_ld;
}

// ---------------- rank-NB trailing update: W = base + F*Wp, full chip ----------------
__global__ void __launch_bounds__(256) upd_k(int k0) {
    int b = blockIdx.z;
    float* W = g_W + (size_t)b * NM;
    const float* F  = g_F  + (size_t)b * NSEQ * NB;
    const float* Wp = g_Wp + (size_t)b * NB * NSEQ;
    __shared__ float Fs[NB][64];
    __shared__ float Bs[NB][64];
    int tid = threadIdx.x;
    int i0 = blockIdx.y * 64, j0 = blockIdx.x * 64;
    {
        int i = tid >> 2, kk = (tid & 3) << 3;
        float4 v1 = *(const float4*)(F + (size_t)(i0 + i) * NB + kk);
        float4 v2 = *(const float4*)(F + (size_t)(i0 + i) * NB + kk + 4);
        Fs[kk+0][i] = v1.x; Fs[kk+1][i] = v1.y; Fs[kk+2][i] = v1.z; Fs[kk+3][i] = v1.w;
        Fs[kk+4][i] = v2.x; Fs[kk+5][i] = v2.y; Fs[kk+6][i] = v2.z; Fs[kk+7][i] = v2.w;
    }
    {
        int kk = tid >> 3, j8 = (tid & 7) << 3;
        *(float4*)&Bs[kk][j8]     = *(const float4*)(Wp + (size_t)kk * NSEQ + j0 + j8);
        *(float4*)&Bs[kk][j8 + 4] = *(const float4*)(Wp + (size_t)kk * NSEQ + j0 + j8 + 4);
    }
    __syncthreads();
    int tx = tid & 15, ty = tid >> 4;
    float acc[4][4] = {};
    #pragma unroll
    for (int kk = 0; kk < NB; kk++) {
        float4 av = *(const float4*)&Fs[kk][ty << 2];
        float4 bv = *(const float4*)&Bs[kk][tx << 2];
        float ar[4] = {av.x, av.y, av.z, av.w};
        float br[4] = {bv.x, bv.y, bv.z, bv.w};
        #pragma unroll
        for (int a = 0; a < 4; a++)
            #pragma unroll
            for (int q = 0; q < 4; q++)
                acc[a][q] = fmaf(ar[a], br[q], acc[a][q]);
    }
    int col = j0 + (tx << 2);
    bool pcol = (col >= k0 && col < k0 + NB);
    if (pcol) return;
    #pragma unroll
    for (int a = 0; a < 4; a++) {
        int row = i0 + (ty << 2) + a;
        bool prow = (row >= k0 && row < k0 + NB);
        float4* wp4 = (float4*)(W + (size_t)row * NSEQ + col);
        float4 r = make_float4(acc[a][0], acc[a][1], acc[a][2], acc[a][3]);
        if (!prow) {
            float4 base = *wp4;
            r.x += base.x; r.y += base.y; r.z += base.z; r.w += base.w;
        }
        *wp4 = r;
    }
}

// ---------------- resolve labels: g_perm = Linv (Linv[L[j]] = j) ----------------
__global__ void __launch_bounds__(512) labels_k() {
    int b = blockIdx.x, tid = threadIdx.x;
    __shared__ int s_L[NSEQ];
    if (tid == 0) {
        for (int j = 0; j < NSEQ; j++) s_L[j] = j;
        for (int k = NSEQ - 1; k >= 0; k--) {
            int p = g_piv[b * NSEQ + k];
            if (p != k) { int t = s_L[k]; s_L[k] = s_L[p]; s_L[p] = t; }
        }
    }
    __syncthreads();
    g_perm[b * NSEQ + s_L[tid]] = tid;
}

// ---------------- coalesced permuted transpose + diag: BT[Linv[j]][i] = C[i][j] ----------------
__global__ void permT_k() {
    int b = blockIdx.z;
    const float* C = g_W + (size_t)b * NM;
    float* BT = g_BT + (size_t)b * NM;
    const int* Linv = g_perm + b * NSEQ;
    __shared__ float sm[32][33];
    int i0 = blockIdx.y * 32, j0 = blockIdx.x * 32;
    int tx = threadIdx.x, ty = threadIdx.y;
    #pragma unroll
    for (int k = 0; k < 4; k++)
        sm[ty + 8*k][tx] = C[(size_t)(i0 + ty + 8*k) * NSEQ + j0 + tx];
    __syncthreads();
    #pragma unroll
    for (int k = 0; k < 4; k++) {
        int j = j0 + ty + 8*k;
        int lj = Linv[j];
        float v = sm[tx][ty + 8*k];
        BT[(size_t)lj * NSEQ + i0 + tx] = v;
        if (lj == i0 + tx) g_diagB[b * NSEQ + lj] = v;
    }
}

// ---------------- marginals Y + fp64 dot(Y, scores) ----------------
__global__ void __launch_bounds__(512) y_k(const int* __restrict__ lengths) {
    int h = blockIdx.x, b = blockIdx.y, m = threadIdx.x;
    int len = lengths[b];
    float c = dec_f(g_cbits[b]);
    float s = g_scores[(size_t)b * NM + (size_t)h * NSEQ + m];
    float y = 0.f;
    if (h <= len && m >= 1 && m <= len && h != m) {
        float A = expf(s - c);
        float diag = (m >= 2) ? g_diagB[b * NSEQ + (m - 1)] : 0.f;
        float G;
        if (h == 0) G = g_BT[(size_t)b * NM + (m - 1)] + diag;   // BT row 0 = Binv[:,0]
        else        G = diag - ((h >= 2) ? g_BT[(size_t)b * NM + (size_t)(h - 1) * NSEQ + (m - 1)] : 0.f);
        y = A * G;
    }
    g_Y[(size_t)b * NM + (size_t)h * NSEQ + m] = y;

    float v = y * s;
    #pragma unroll
    for (int o = 16; o; o >>= 1) v += __shfl_down_sync(0xffffffffu, v, o);
    __shared__ float ws[16];
    if ((m & 31) == 0) ws[m >> 5] = v;
    __syncthreads();
    if (m < 16) {
        v = ws[m];
        #pragma unroll
        for (int o = 8; o; o >>= 1) v += __shfl_down_sync(0xffffu, v, o);
        if (m == 0) atomicAdd(&g_dotp[b], (double)v);
    }
}

__global__ void fin_k(const int* __restrict__ lengths, float* __restrict__ out) {
    int b = threadIdx.x;
    if (b < BB) {
        float logZ = (float)g_logdet[b] + (float)lengths[b] * dec_f(g_cbits[b]);
        out[(size_t)BB * NM + b] = logZ;
        out[(size_t)2 * BB * NM + BB + b] = logZ - (float)g_dotp[b];
    }
}

extern "C" void kernel_launch(void* const* d_in, const int* in_sizes, int n_in,
                              void* d_out, int out_size) {
    const float* Xh = (const float*)d_in[0];
    const float* Xm = (const float*)d_in[1];
    const int*   lengths = (const int*)d_in[2];
    const float* Wh = (const float*)d_in[3];
    const float* bh = (const float*)d_in[4];
    const float* Wm = (const float*)d_in[5];
    const float* bm = (const float*)d_in[6];
    const float* V  = (const float*)d_in[7];
    float* out = (float*)d_out;

    void* p;
    cudaGetSymbolAddress(&p, g_H0);     float* pH0 = (float*)p;
    cudaGetSymbolAddress(&p, g_M0);     float* pM0 = (float*)p;
    cudaGetSymbolAddress(&p, g_Hb);     float* pHb = (float*)p;
    cudaGetSymbolAddress(&p, g_Mb);     float* pMb = (float*)p;
    cudaGetSymbolAddress(&p, g_T);      float* pT  = (float*)p;
    cudaGetSymbolAddress(&p, g_scores); float* pSc = (float*)p;
    cudaGetSymbolAddress(&p, g_Y);      float* pY  = (float*)p;

    dim3 gProj(DH / 64, (BB * NSEQ) / 64, 1);

    gemm_k<false, true, 1><<<gProj, 256>>>(Xh, Wh, bh, pH0, BB*NSEQ, DH, DIN, DIN, DIN, DH, 0, 0, 0);
    gemm_k<false, true, 1><<<gProj, 256>>>(Xm, Wm, bm, pM0, BB*NSEQ, DH, DIN, DIN, DIN, DH, 0, 0, 0);
    relu_k<<<(HS + 255) / 256, 256>>>(pH0, pHb, HS);
    relu_k<<<(HS + 255) / 256, 256>>>(pM0, pMb, HS);

    dim3 g128(DH / 64, (BB * NSEQ) / 128, 1);     // (2,128,1) for flattened 16384xDH
    dim3 gSc(NSEQ / 64, NSEQ / 128, BB);          // (8,4,32) batched 512x512
    dim3 gYM(DH / 64, NSEQ / 128, BB);            // (2,4,32) batched 512x128

    for (int it = 0; it < NITER; it++) {
        float* H = pHb + (size_t)(it & 1) * HS;
        float* M = pMb + (size_t)(it & 1) * HS;
        init_k<<<1, BB>>>();
        // T = H @ V
        gemm128_k<false, false, 0><<<g128, 256>>>(H, V, nullptr, pT, DH, DH, DH, DH, 0, 0, 0, nullptr);
        // scores = T @ M^T (batched) + fused masked max
        gemm128_k<false, true, 3><<<gSc, 256>>>(pT, M, nullptr, pSc, DH, DH, DH, NSEQ,
                                                (long)NSEQ*DH, (long)NSEQ*DH, (long)NM, lengths);
        colsum_k<<<BB, NSEQ>>>(lengths);
        lhat_k<<<dim3(NSEQ, BB), NSEQ>>>(lengths);
        for (int k0 = 0; k0 < NSEQ; k0 += NB) {
            panel_k<<<BB, 512>>>(k0);
            upd_k<<<dim3(8, 8, BB), 256>>>(k0);
        }
        labels_k<<<BB, 512>>>();
        permT_k<<<dim3(16, 16, BB), dim3(32, 8)>>>();
        y_k<<<dim3(NSEQ, BB), NSEQ>>>(lengths);

        if (it < NITER - 1) {
            float* Hn = pHb + (size_t)((it + 1) & 1) * HS;
            float* Mn = pMb + (size_t)((it + 1) & 1) * HS;
            // T = Y @ M (batched)
            gemm128_k<false, false, 0><<<gYM, 256>>>(pY, M, nullptr, pT, NSEQ, NSEQ, DH, DH,
                                                     (long)NM, (long)NSEQ*DH, (long)NSEQ*DH, nullptr);
            // Hn = relu(H0 + T @ V^T)
            gemm128_k<false, true, 2><<<g128, 256>>>(pT, V, pH0, Hn, DH, DH, DH, DH, 0, 0, 0, nullptr);
            // T = Y^T @ H (batched)
            gemm128_k<true, false, 0><<<gYM, 256>>>(pY, H, nullptr, pT, NSEQ, NSEQ, DH, DH,
                                                    (long)NM, (long)NSEQ*DH, (long)NSEQ*DH, nullptr);
            // Mn = relu(M0 + T @ V)
            gemm128_k<false, false, 2><<<g128, 256>>>(pT, V, pM0, Mn, DH, DH, DH, DH, 0, 0, 0, nullptr);
        }
    }

    fin_k<<<1, BB>>>(lengths, out);
    cudaMemcpyAsync(out, pSc, (size_t)BB * NM * sizeof(float), cudaMemcpyDeviceToDevice, 0);
    cudaMemcpyAsync(out + (size_t)BB * NM + BB, pY, (size_t)BB * NM * sizeof(float), cudaMemcpyDeviceToDevice, 0);
}